// round 3
// baseline (speedup 1.0000x reference)
#include <cuda_runtime.h>
#include <stdint.h>
#include <math.h>

#define BATCH 4
#define SLEN  2048
#define EMBED 1024
#define NHEAD 16
#define HDIM  64
#define NTOK  (BATCH * SLEN)     // 8192
#define QKVN  (3 * EMBED)        // 3072

// Scratch (static device globals — allocation APIs are forbidden)
__device__ float g_Q[(size_t)BATCH * NHEAD * SLEN * HDIM];
__device__ float g_K[(size_t)BATCH * NHEAD * SLEN * HDIM];
__device__ float g_V[(size_t)BATCH * NHEAD * SLEN * HDIM];
__device__ float g_O[(size_t)NTOK * EMBED];

// ---------------------------------------------------------------------------
// tf32 helpers
// ---------------------------------------------------------------------------
__device__ __forceinline__ uint32_t f2tf32(float f) {
    uint32_t r;
    asm("cvt.rna.tf32.f32 %0, %1;" : "=r"(r) : "f"(f));
    return r;
}

__device__ __forceinline__ void mma_tf32(float* d, const uint32_t* a, const uint32_t* b) {
    asm volatile(
        "mma.sync.aligned.m16n8k8.row.col.f32.tf32.tf32.f32 "
        "{%0,%1,%2,%3},{%4,%5,%6,%7},{%8,%9},{%0,%1,%2,%3};"
        : "+f"(d[0]), "+f"(d[1]), "+f"(d[2]), "+f"(d[3])
        : "r"(a[0]), "r"(a[1]), "r"(a[2]), "r"(a[3]), "r"(b[0]), "r"(b[1]));
}

// ---------------------------------------------------------------------------
// 3xTF32 GEMM: C[M,N] = A[M,K] @ B[K,N].  BM=BN=128, BK=16, 256 threads.
// 8 warps = 2(M) x 4(N); warp tile 64x32; per warp 4 m-tiles x 4 n-tiles.
// hi/lo split: D += Ah*Bh + Ah*Bl + Al*Bh  (fp32-class accuracy).
// MODE 0: scatter epilogue de-interleaving (H, D, 3) packing into Q/K/V.
// MODE 1: plain float2 stores into C.
// ---------------------------------------------------------------------------
template <int MODE>
__global__ void __launch_bounds__(256)
gemm3x_kernel(const float* __restrict__ A, const float* __restrict__ B,
              float* __restrict__ C,
              float* __restrict__ Qo, float* __restrict__ Ko, float* __restrict__ Vo,
              int M, int N, int K)
{
    __shared__ uint32_t Ah[16][132], Al[16][132];   // k-major (transposed) A
    __shared__ uint32_t Bh[16][132], Bl[16][132];   // k-major B

    const int tid  = threadIdx.x;
    const int lane = tid & 31;
    const int warp = tid >> 5;
    const int wm = warp >> 2;          // 0..1
    const int wn = warp & 3;           // 0..3
    const int g  = lane >> 2;          // group id 0..7
    const int t  = lane & 3;           // thread-in-group 0..3
    const int bm = blockIdx.y;
    const int bn = blockIdx.x;

    const float* Ab = A + (size_t)bm * 128 * K;
    const float* Bb = B + (size_t)bn * 128;

    float acc[4][4][4];
#pragma unroll
    for (int mt = 0; mt < 4; mt++)
#pragma unroll
        for (int nt = 0; nt < 4; nt++)
#pragma unroll
            for (int e = 0; e < 4; e++) acc[mt][nt][e] = 0.0f;

    for (int k0 = 0; k0 < K; k0 += 16) {
        float4 av[2], bv[2];
#pragma unroll
        for (int r = 0; r < 2; r++) {
            int i = tid + r * 256;
            int arow = i >> 2, ac = (i & 3) * 4;
            av[r] = *(const float4*)(Ab + (size_t)arow * K + k0 + ac);
            int brow = i >> 5, bc = (i & 31) * 4;
            bv[r] = *(const float4*)(Bb + (size_t)(k0 + brow) * N + bc);
        }
        __syncthreads();
#pragma unroll
        for (int r = 0; r < 2; r++) {
            int i = tid + r * 256;
            int arow = i >> 2, ac = (i & 3) * 4;
            float va[4] = {av[r].x, av[r].y, av[r].z, av[r].w};
#pragma unroll
            for (int j = 0; j < 4; j++) {
                uint32_t hi = f2tf32(va[j]);
                uint32_t lo = f2tf32(va[j] - __uint_as_float(hi));
                Ah[ac + j][arow] = hi;
                Al[ac + j][arow] = lo;
            }
            int brow = i >> 5, bc = (i & 31) * 4;
            float vb[4] = {bv[r].x, bv[r].y, bv[r].z, bv[r].w};
            uint4 bh4, bl4;
            {
                uint32_t h0 = f2tf32(vb[0]), h1 = f2tf32(vb[1]), h2 = f2tf32(vb[2]), h3 = f2tf32(vb[3]);
                bh4 = make_uint4(h0, h1, h2, h3);
                bl4 = make_uint4(f2tf32(vb[0] - __uint_as_float(h0)),
                                 f2tf32(vb[1] - __uint_as_float(h1)),
                                 f2tf32(vb[2] - __uint_as_float(h2)),
                                 f2tf32(vb[3] - __uint_as_float(h3)));
            }
            *(uint4*)&Bh[brow][bc] = bh4;
            *(uint4*)&Bl[brow][bc] = bl4;
        }
        __syncthreads();

#pragma unroll
        for (int ks = 0; ks < 2; ks++) {
            const int kb = ks * 8;
            uint32_t ah[4][4], al[4][4], bh[4][2], bl[4][2];
#pragma unroll
            for (int mt = 0; mt < 4; mt++) {
                int m0 = wm * 64 + mt * 16 + g;
                int kk = kb + t;
                ah[mt][0] = Ah[kk][m0];     ah[mt][1] = Ah[kk][m0 + 8];
                ah[mt][2] = Ah[kk + 4][m0]; ah[mt][3] = Ah[kk + 4][m0 + 8];
                al[mt][0] = Al[kk][m0];     al[mt][1] = Al[kk][m0 + 8];
                al[mt][2] = Al[kk + 4][m0]; al[mt][3] = Al[kk + 4][m0 + 8];
            }
#pragma unroll
            for (int nt = 0; nt < 4; nt++) {
                int n0 = wn * 32 + nt * 8 + g;
                bh[nt][0] = Bh[kb + t][n0];     bh[nt][1] = Bh[kb + t + 4][n0];
                bl[nt][0] = Bl[kb + t][n0];     bl[nt][1] = Bl[kb + t + 4][n0];
            }
#pragma unroll
            for (int mt = 0; mt < 4; mt++)
#pragma unroll
                for (int nt = 0; nt < 4; nt++) {
                    mma_tf32(acc[mt][nt], ah[mt], bh[nt]);
                    mma_tf32(acc[mt][nt], ah[mt], bl[nt]);
                    mma_tf32(acc[mt][nt], al[mt], bh[nt]);
                }
        }
    }

    if (MODE == 0) {
#pragma unroll
        for (int mt = 0; mt < 4; mt++)
#pragma unroll
            for (int nt = 0; nt < 4; nt++) {
                int r0 = bm * 128 + wm * 64 + mt * 16 + g;
                int c0 = bn * 128 + wn * 32 + nt * 8 + 2 * t;
#pragma unroll
                for (int e = 0; e < 4; e++) {
                    int row = r0 + (e >> 1) * 8;
                    int col = c0 + (e & 1);
                    int b_  = row >> 11;
                    int s   = row & 2047;
                    int h   = col / 192;
                    int rem = col - h * 192;
                    int d   = rem / 3;
                    int w   = rem - d * 3;
                    float* dst = (w == 0) ? Qo : (w == 1) ? Ko : Vo;
                    dst[(((size_t)b_ * NHEAD + h) * SLEN + s) * HDIM + d] = acc[mt][nt][e];
                }
            }
    } else {
#pragma unroll
        for (int mt = 0; mt < 4; mt++)
#pragma unroll
            for (int nt = 0; nt < 4; nt++) {
                size_t r = (size_t)(bm * 128 + wm * 64 + mt * 16 + g);
                int    c = bn * 128 + wn * 32 + nt * 8 + 2 * t;
                *(float2*)&C[r * N + c]       = make_float2(acc[mt][nt][0], acc[mt][nt][1]);
                *(float2*)&C[(r + 8) * N + c] = make_float2(acc[mt][nt][2], acc[mt][nt][3]);
            }
    }
}

// ---------------------------------------------------------------------------
// Flash attention, tf32 tensor cores. BQ=128, BKEY=64, D=64. 256 thr = 8 warps.
// Warps 4(q) x 2(col): warp tile 32 rows x 32 cols for both S and O.
// Softmax in fp32 by row-owner threads (2 threads/row); P stored as tf32 bits.
// ---------------------------------------------------------------------------
#define LDA 68   // u32 stride for all smem tiles

__global__ void __launch_bounds__(256)
attn_tc_kernel(const float* __restrict__ Q, const float* __restrict__ K,
               const float* __restrict__ V, float* __restrict__ O)
{
    extern __shared__ uint32_t smu[];
    uint32_t* Qs = smu;                      // [128][LDA] tf32
    uint32_t* Ks = Qs + 128 * LDA;           // [64][LDA]  tf32
    uint32_t* Vs = Ks + 64 * LDA;            // [64][LDA]  tf32
    float*    Ssf = (float*)(Vs + 64 * LDA); // [128][LDA] fp32 scores -> tf32 P
    uint32_t* Psu = (uint32_t*)Ssf;
    float*    alpha_sm = Ssf + 128 * LDA;    // [128]
    float*    linv_sm  = alpha_sm + 128;     // [128]

    const int tid  = threadIdx.x;
    const int lane = tid & 31;
    const int warp = tid >> 5;
    const int wq = warp >> 1;                // 0..3 (row block)
    const int wk = warp & 1;                 // 0..1 (col block)
    const int g  = lane >> 2;
    const int t  = lane & 3;
    const int qblk = blockIdx.x;
    const int bh   = blockIdx.y;

    const float* Qg = Q + ((size_t)bh * SLEN + qblk * 128) * HDIM;
    const float* Kg = K + (size_t)bh * SLEN * HDIM;
    const float* Vg = V + (size_t)bh * SLEN * HDIM;
    const float qscale = 1.0f / 32.0f;       // 1/sqrt(1024)

    // load Q once (scaled, tf32)
#pragma unroll
    for (int r = 0; r < 8; r++) {
        int i = tid + r * 256;               // 0..2047
        int row = i >> 4, c4 = (i & 15) * 4;
        float4 v = *(const float4*)(Qg + (size_t)row * HDIM + c4);
        Qs[row * LDA + c4 + 0] = f2tf32(v.x * qscale);
        Qs[row * LDA + c4 + 1] = f2tf32(v.y * qscale);
        Qs[row * LDA + c4 + 2] = f2tf32(v.z * qscale);
        Qs[row * LDA + c4 + 3] = f2tf32(v.w * qscale);
    }

    // softmax row-owner state: row = tid>>1, half = tid&1
    const int srow = tid >> 1;
    const int shf  = tid & 1;
    float m_r = -1e30f, l_r = 0.0f;

    // O accumulators: [mt 2][nt 4][4]
    float acc[2][4][4];
#pragma unroll
    for (int mt = 0; mt < 2; mt++)
#pragma unroll
        for (int nt = 0; nt < 4; nt++)
#pragma unroll
            for (int e = 0; e < 4; e++) acc[mt][nt][e] = 0.0f;

    for (int kb = 0; kb < SLEN / 64; kb++) {
        __syncthreads();   // previous iteration's Ps/Vs reads done
        const float* Kgb = Kg + (size_t)kb * 64 * HDIM;
        const float* Vgb = Vg + (size_t)kb * 64 * HDIM;
#pragma unroll
        for (int r = 0; r < 4; r++) {
            int i = tid + r * 256;           // 0..1023
            int row = i >> 4, c4 = (i & 15) * 4;
            float4 kv = *(const float4*)(Kgb + (size_t)row * HDIM + c4);
            float4 vv = *(const float4*)(Vgb + (size_t)row * HDIM + c4);
            Ks[row * LDA + c4 + 0] = f2tf32(kv.x);
            Ks[row * LDA + c4 + 1] = f2tf32(kv.y);
            Ks[row * LDA + c4 + 2] = f2tf32(kv.z);
            Ks[row * LDA + c4 + 3] = f2tf32(kv.w);
            Vs[row * LDA + c4 + 0] = f2tf32(vv.x);
            Vs[row * LDA + c4 + 1] = f2tf32(vv.y);
            Vs[row * LDA + c4 + 2] = f2tf32(vv.z);
            Vs[row * LDA + c4 + 3] = f2tf32(vv.w);
        }
        __syncthreads();

        // S = Qs @ Ks^T
        float s[2][4][4];
#pragma unroll
        for (int mt = 0; mt < 2; mt++)
#pragma unroll
            for (int nt = 0; nt < 4; nt++)
#pragma unroll
                for (int e = 0; e < 4; e++) s[mt][nt][e] = 0.0f;

#pragma unroll
        for (int ks = 0; ks < 8; ks++) {
            const int kb2 = ks * 8;
            uint32_t aq[2][4];
#pragma unroll
            for (int mt = 0; mt < 2; mt++) {
                int m0 = wq * 32 + mt * 16 + g;
                int kk = kb2 + t;
                aq[mt][0] = Qs[m0 * LDA + kk];
                aq[mt][1] = Qs[(m0 + 8) * LDA + kk];
                aq[mt][2] = Qs[m0 * LDA + kk + 4];
                aq[mt][3] = Qs[(m0 + 8) * LDA + kk + 4];
            }
#pragma unroll
            for (int nt = 0; nt < 4; nt++) {
                int n0 = wk * 32 + nt * 8 + g;
                uint32_t bk[2];
                bk[0] = Ks[n0 * LDA + kb2 + t];
                bk[1] = Ks[n0 * LDA + kb2 + 4 + t];
                mma_tf32(s[0][nt], aq[0], bk);
                mma_tf32(s[1][nt], aq[1], bk);
            }
        }

        // write scores (fp32)
#pragma unroll
        for (int mt = 0; mt < 2; mt++)
#pragma unroll
            for (int nt = 0; nt < 4; nt++) {
                int r0 = wq * 32 + mt * 16 + g;
                int c0 = wk * 32 + nt * 8 + 2 * t;
                Ssf[r0 * LDA + c0]           = s[mt][nt][0];
                Ssf[r0 * LDA + c0 + 1]       = s[mt][nt][1];
                Ssf[(r0 + 8) * LDA + c0]     = s[mt][nt][2];
                Ssf[(r0 + 8) * LDA + c0 + 1] = s[mt][nt][3];
            }
        __syncthreads();

        // online softmax: 2 threads per row
        {
            float* rowp = Ssf + srow * LDA + shf * 32;
            float4* rp4 = (float4*)rowp;
            float mx = -1e30f;
#pragma unroll
            for (int j = 0; j < 8; j++) {
                float4 v = rp4[j];
                mx = fmaxf(mx, fmaxf(fmaxf(v.x, v.y), fmaxf(v.z, v.w)));
            }
            mx = fmaxf(mx, __shfl_xor_sync(0xffffffffu, mx, 1));
            float mn = fmaxf(m_r, mx);
            float alpha = __expf(m_r - mn);
            m_r = mn;
            float sum = 0.0f;
            uint4* rpu = (uint4*)rowp;
#pragma unroll
            for (int j = 0; j < 8; j++) {
                float4 v = rp4[j];
                float e0 = __expf(v.x - mn), e1 = __expf(v.y - mn);
                float e2 = __expf(v.z - mn), e3 = __expf(v.w - mn);
                sum += (e0 + e1) + (e2 + e3);
                rpu[j] = make_uint4(f2tf32(e0), f2tf32(e1), f2tf32(e2), f2tf32(e3));
            }
            sum += __shfl_xor_sync(0xffffffffu, sum, 1);
            l_r = l_r * alpha + sum;
            if (shf == 0) alpha_sm[srow] = alpha;
        }
        __syncthreads();

        // rescale O accumulators, then O += P @ V
#pragma unroll
        for (int mt = 0; mt < 2; mt++) {
            int r0 = wq * 32 + mt * 16 + g;
            float a0 = alpha_sm[r0], a1 = alpha_sm[r0 + 8];
#pragma unroll
            for (int nt = 0; nt < 4; nt++) {
                acc[mt][nt][0] *= a0; acc[mt][nt][1] *= a0;
                acc[mt][nt][2] *= a1; acc[mt][nt][3] *= a1;
            }
        }
#pragma unroll
        for (int ks = 0; ks < 8; ks++) {
            const int kb2 = ks * 8;
            uint32_t ap[2][4];
#pragma unroll
            for (int mt = 0; mt < 2; mt++) {
                int m0 = wq * 32 + mt * 16 + g;
                int kk = kb2 + t;
                ap[mt][0] = Psu[m0 * LDA + kk];
                ap[mt][1] = Psu[(m0 + 8) * LDA + kk];
                ap[mt][2] = Psu[m0 * LDA + kk + 4];
                ap[mt][3] = Psu[(m0 + 8) * LDA + kk + 4];
            }
#pragma unroll
            for (int nt = 0; nt < 4; nt++) {
                int n0 = wk * 32 + nt * 8 + g;     // d dim
                uint32_t bv_[2];
                bv_[0] = Vs[(kb2 + t) * LDA + n0];
                bv_[1] = Vs[(kb2 + 4 + t) * LDA + n0];
                mma_tf32(acc[0][nt], ap[0], bv_);
                mma_tf32(acc[1][nt], ap[1], bv_);
            }
        }
    }

    // finalize
    if (shf == 0) linv_sm[srow] = 1.0f / l_r;
    __syncthreads();

    const int b_ = bh >> 4;
    const int h  = bh & 15;
#pragma unroll
    for (int mt = 0; mt < 2; mt++) {
        int r0 = wq * 32 + mt * 16 + g;
        float i0 = linv_sm[r0], i1 = linv_sm[r0 + 8];
        size_t tok0 = (size_t)b_ * SLEN + qblk * 128 + r0;
#pragma unroll
        for (int nt = 0; nt < 4; nt++) {
            int c = wk * 32 + nt * 8 + 2 * t;
            *(float2*)&O[tok0 * EMBED + h * 64 + c] =
                make_float2(acc[mt][nt][0] * i0, acc[mt][nt][1] * i0);
            *(float2*)&O[(tok0 + 8) * EMBED + h * 64 + c] =
                make_float2(acc[mt][nt][2] * i1, acc[mt][nt][3] * i1);
        }
    }
}

// ---------------------------------------------------------------------------
extern "C" void kernel_launch(void* const* d_in, const int* in_sizes, int n_in,
                              void* d_out, int out_size)
{
    const float* x    = (const float*)d_in[0];   // [4,2048,1024]
    const float* Wqkv = (const float*)d_in[1];   // [1024,3072]
    const float* Wout = (const float*)d_in[2];   // [1024,1024]
    float* out = (float*)d_out;                  // [4,2048,1024]

    float *Qp, *Kp, *Vp, *Op;
    cudaGetSymbolAddress((void**)&Qp, g_Q);
    cudaGetSymbolAddress((void**)&Kp, g_K);
    cudaGetSymbolAddress((void**)&Vp, g_V);
    cudaGetSymbolAddress((void**)&Op, g_O);

    // attention dynamic smem: Qs + Ks + Vs + Ss + alpha + linv (u32 units)
    const int attn_smem = (128 * LDA + 64 * LDA + 64 * LDA + 128 * LDA + 256) * 4;
    static bool configured = false;
    if (!configured) {
        cudaFuncSetAttribute(attn_tc_kernel,
                             cudaFuncAttributeMaxDynamicSharedMemorySize, attn_smem);
        configured = true;
    }

    // 1) QKV projection (3xTF32) + de-interleave into Q/K/V [b,h,s,d]
    dim3 g1(QKVN / 128, NTOK / 128);   // (24, 64)
    gemm3x_kernel<0><<<g1, 256>>>(x, Wqkv, nullptr, Qp, Kp, Vp, NTOK, QKVN, EMBED);

    // 2) tensor-core flash attention -> g_O [token, E]
    dim3 g2(SLEN / 128, BATCH * NHEAD); // (16, 64)
    attn_tc_kernel<<<g2, 256, attn_smem>>>(Qp, Kp, Vp, Op);

    // 3) output projection (3xTF32)
    dim3 g3(EMBED / 128, NTOK / 128);  // (8, 64)
    gemm3x_kernel<1><<<g3, 256>>>(Op, Wout, out, nullptr, nullptr, nullptr, NTOK, EMBED, EMBED);
}

// round 4
// speedup vs baseline: 1.6825x; 1.6825x over previous
#include <cuda_runtime.h>
#include <cuda_bf16.h>
#include <stdint.h>
#include <math.h>

#define BATCH 4
#define SLEN  2048
#define EMBED 1024
#define NHEAD 16
#define HDIM  64
#define NTOK  (BATCH * SLEN)     // 8192
#define QKVN  (3 * EMBED)        // 3072

__device__ float g_Q[(size_t)BATCH * NHEAD * SLEN * HDIM];
__device__ float g_K[(size_t)BATCH * NHEAD * SLEN * HDIM];
__device__ float g_V[(size_t)BATCH * NHEAD * SLEN * HDIM];
__device__ __nv_bfloat16 g_xh[(size_t)NTOK * EMBED],  g_xl[(size_t)NTOK * EMBED];
__device__ __nv_bfloat16 g_oh[(size_t)NTOK * EMBED],  g_ol[(size_t)NTOK * EMBED];
__device__ __nv_bfloat16 g_wqh[(size_t)EMBED * QKVN], g_wql[(size_t)EMBED * QKVN];
__device__ __nv_bfloat16 g_woh[(size_t)EMBED * EMBED], g_wol[(size_t)EMBED * EMBED];

// ------------------------------ helpers ------------------------------------
__device__ __forceinline__ uint32_t f2tf32(float f) {
    uint32_t r; asm("cvt.rna.tf32.f32 %0, %1;" : "=r"(r) : "f"(f)); return r;
}
__device__ __forceinline__ void mma_tf32(float* d, const uint32_t* a, const uint32_t* b) {
    asm volatile("mma.sync.aligned.m16n8k8.row.col.f32.tf32.tf32.f32 "
        "{%0,%1,%2,%3},{%4,%5,%6,%7},{%8,%9},{%0,%1,%2,%3};"
        : "+f"(d[0]), "+f"(d[1]), "+f"(d[2]), "+f"(d[3])
        : "r"(a[0]), "r"(a[1]), "r"(a[2]), "r"(a[3]), "r"(b[0]), "r"(b[1]));
}
__device__ __forceinline__ void mma_bf16(float* d, const uint32_t* a, const uint32_t* b) {
    asm volatile("mma.sync.aligned.m16n8k16.row.col.f32.bf16.bf16.f32 "
        "{%0,%1,%2,%3},{%4,%5,%6,%7},{%8,%9},{%0,%1,%2,%3};"
        : "+f"(d[0]), "+f"(d[1]), "+f"(d[2]), "+f"(d[3])
        : "r"(a[0]), "r"(a[1]), "r"(a[2]), "r"(a[3]), "r"(b[0]), "r"(b[1]));
}
__device__ __forceinline__ uint32_t s2u(const void* p) {
    uint32_t a;
    asm("{ .reg .u64 t; cvta.to.shared.u64 t, %1; cvt.u32.u64 %0, t; }" : "=r"(a) : "l"(p));
    return a;
}
__device__ __forceinline__ void ldm_x4(uint32_t* r, uint32_t a) {
    asm volatile("ldmatrix.sync.aligned.m8n8.x4.shared.b16 {%0,%1,%2,%3},[%4];"
        : "=r"(r[0]), "=r"(r[1]), "=r"(r[2]), "=r"(r[3]) : "r"(a));
}
__device__ __forceinline__ void ldm_x2t(uint32_t* r, uint32_t a) {
    asm volatile("ldmatrix.sync.aligned.m8n8.x2.trans.shared.b16 {%0,%1},[%2];"
        : "=r"(r[0]), "=r"(r[1]) : "r"(a));
}
__device__ __forceinline__ void split2(float a, float b, uint32_t& hi, uint32_t& lo) {
    __nv_bfloat16 ha = __float2bfloat16(a), hb = __float2bfloat16(b);
    __nv_bfloat16 la = __float2bfloat16(a - __bfloat162float(ha));
    __nv_bfloat16 lb = __float2bfloat16(b - __bfloat162float(hb));
    hi = (uint32_t)__bfloat16_as_ushort(ha) | ((uint32_t)__bfloat16_as_ushort(hb) << 16);
    lo = (uint32_t)__bfloat16_as_ushort(la) | ((uint32_t)__bfloat16_as_ushort(lb) << 16);
}

// elementwise hi/lo split (no transpose)
__global__ void __launch_bounds__(256)
conv_split(const float* __restrict__ X, __nv_bfloat16* __restrict__ Xh,
           __nv_bfloat16* __restrict__ Xl, int n4)
{
    int i = blockIdx.x * blockDim.x + threadIdx.x;
    if (i >= n4) return;
    float4 v = ((const float4*)X)[i];
    uint32_t h0, l0, h1, l1;
    split2(v.x, v.y, h0, l0);
    split2(v.z, v.w, h1, l1);
    ((uint2*)Xh)[i] = make_uint2(h0, h1);
    ((uint2*)Xl)[i] = make_uint2(l0, l1);
}

// ---------------------------------------------------------------------------
// bf16 3-term split GEMM: C = A@B, A[M,K] row-major hi/lo, B[K,N] hi/lo.
// BM=BN=128, BK=32, 256 thr, 8 warps 2x4, warp 64x32, m16n8k16.
// MODE 0: de-interleave scatter into Q/K/V.  MODE 1: fp32 store.
// ---------------------------------------------------------------------------
#define ALD 40    // A smem stride (bf16), conflict-free for ldmatrix
#define BLD 136   // B smem stride (bf16)

template <int MODE>
__global__ void __launch_bounds__(256, 2)
gemm_bf16_kernel(const __nv_bfloat16* __restrict__ Ah, const __nv_bfloat16* __restrict__ Al,
                 const __nv_bfloat16* __restrict__ Bh, const __nv_bfloat16* __restrict__ Bl,
                 float* __restrict__ C,
                 float* __restrict__ Qo, float* __restrict__ Ko, float* __restrict__ Vo,
                 int M, int N, int K)
{
    __shared__ __nv_bfloat16 sAh[128][ALD], sAl[128][ALD];
    __shared__ __nv_bfloat16 sBh[32][BLD],  sBl[32][BLD];

    const int tid = threadIdx.x, lane = tid & 31, warp = tid >> 5;
    const int wm = warp >> 2, wn = warp & 3;
    const int g = lane >> 2, t = lane & 3;
    const int bm = blockIdx.y, bn = blockIdx.x;
    const int m0 = bm * 128, n0 = bn * 128;

    // ldmatrix lane addressing
    const int arow = wm * 64 + (lane & 7) + ((lane >> 3) & 1) * 8;  // + mt*16
    const int acol = (lane >> 4) * 8;                               // + ks*16
    const int krow = (lane & 7) + ((lane >> 3) & 1) * 8;            // + ks*16

    float acc[4][4][4];
#pragma unroll
    for (int mt = 0; mt < 4; mt++)
#pragma unroll
        for (int nt = 0; nt < 4; nt++)
#pragma unroll
            for (int e = 0; e < 4; e++) acc[mt][nt][e] = 0.0f;

    for (int k0 = 0; k0 < K; k0 += 32) {
        uint4 rah[2], ral[2], rbh[2], rbl[2];
#pragma unroll
        for (int r = 0; r < 2; r++) {
            int id = tid + r * 256;
            int ar = id >> 2, ac = (id & 3) * 8;          // A: 128 rows x 32k
            rah[r] = *(const uint4*)(Ah + (size_t)(m0 + ar) * K + k0 + ac);
            ral[r] = *(const uint4*)(Al + (size_t)(m0 + ar) * K + k0 + ac);
            int br = id >> 4, bc = (id & 15) * 8;         // B: 32k x 128 n
            rbh[r] = *(const uint4*)(Bh + (size_t)(k0 + br) * N + n0 + bc);
            rbl[r] = *(const uint4*)(Bl + (size_t)(k0 + br) * N + n0 + bc);
        }
        __syncthreads();
#pragma unroll
        for (int r = 0; r < 2; r++) {
            int id = tid + r * 256;
            int ar = id >> 2, ac = (id & 3) * 8;
            *(uint4*)&sAh[ar][ac] = rah[r];
            *(uint4*)&sAl[ar][ac] = ral[r];
            int br = id >> 4, bc = (id & 15) * 8;
            *(uint4*)&sBh[br][bc] = rbh[r];
            *(uint4*)&sBl[br][bc] = rbl[r];
        }
        __syncthreads();

#pragma unroll
        for (int ks = 0; ks < 2; ks++) {
            uint32_t ah[4][4], al[4][4];
#pragma unroll
            for (int mt = 0; mt < 4; mt++) {
                ldm_x4(ah[mt], s2u(&sAh[arow + mt * 16][acol + ks * 16]));
                ldm_x4(al[mt], s2u(&sAl[arow + mt * 16][acol + ks * 16]));
            }
#pragma unroll
            for (int nt = 0; nt < 4; nt++) {
                int nb = wn * 32 + nt * 8;
                uint32_t bh[2], bl[2];
                ldm_x2t(bh, s2u(&sBh[ks * 16 + krow][nb]));
                ldm_x2t(bl, s2u(&sBl[ks * 16 + krow][nb]));
#pragma unroll
                for (int mt = 0; mt < 4; mt++) {
                    mma_bf16(acc[mt][nt], ah[mt], bh);
                    mma_bf16(acc[mt][nt], ah[mt], bl);
                    mma_bf16(acc[mt][nt], al[mt], bh);
                }
            }
        }
    }

    if (MODE == 0) {
#pragma unroll
        for (int mt = 0; mt < 4; mt++)
#pragma unroll
            for (int nt = 0; nt < 4; nt++) {
                int r0 = m0 + wm * 64 + mt * 16 + g;
                int c0 = n0 + wn * 32 + nt * 8 + 2 * t;
#pragma unroll
                for (int e = 0; e < 4; e++) {
                    int row = r0 + (e >> 1) * 8;
                    int col = c0 + (e & 1);
                    int b_ = row >> 11, s = row & 2047;
                    int h  = col / 192;
                    int rem = col - h * 192;
                    int d = rem / 3, w = rem - d * 3;
                    float* dst = (w == 0) ? Qo : (w == 1) ? Ko : Vo;
                    dst[(((size_t)b_ * NHEAD + h) * SLEN + s) * HDIM + d] = acc[mt][nt][e];
                }
            }
    } else {
#pragma unroll
        for (int mt = 0; mt < 4; mt++)
#pragma unroll
            for (int nt = 0; nt < 4; nt++) {
                size_t r = (size_t)(m0 + wm * 64 + mt * 16 + g);
                int    c = n0 + wn * 32 + nt * 8 + 2 * t;
                *(float2*)&C[r * N + c]       = make_float2(acc[mt][nt][0], acc[mt][nt][1]);
                *(float2*)&C[(r + 8) * N + c] = make_float2(acc[mt][nt][2], acc[mt][nt][3]);
            }
    }
}

// ---------------------------------------------------------------------------
// Flash attention (tf32 mma.sync), BQ=128, BKEY=64. Epilogue -> bf16 hi/lo.
// ---------------------------------------------------------------------------
#define LDA 68

__global__ void __launch_bounds__(256)
attn_tc_kernel(const float* __restrict__ Q, const float* __restrict__ K,
               const float* __restrict__ V,
               __nv_bfloat16* __restrict__ Oh, __nv_bfloat16* __restrict__ Ol)
{
    extern __shared__ uint32_t smu[];
    uint32_t* Qs = smu;
    uint32_t* Ks = Qs + 128 * LDA;
    uint32_t* Vs = Ks + 64 * LDA;
    float*    Ssf = (float*)(Vs + 64 * LDA);
    uint32_t* Psu = (uint32_t*)Ssf;
    float*    alpha_sm = Ssf + 128 * LDA;
    float*    linv_sm  = alpha_sm + 128;

    const int tid = threadIdx.x, lane = tid & 31, warp = tid >> 5;
    const int wq = warp >> 1, wk = warp & 1;
    const int g = lane >> 2, t = lane & 3;
    const int qblk = blockIdx.x, bh = blockIdx.y;

    const float* Qg = Q + ((size_t)bh * SLEN + qblk * 128) * HDIM;
    const float* Kg = K + (size_t)bh * SLEN * HDIM;
    const float* Vg = V + (size_t)bh * SLEN * HDIM;
    const float qscale = 1.0f / 32.0f;

#pragma unroll
    for (int r = 0; r < 8; r++) {
        int i = tid + r * 256;
        int row = i >> 4, c4 = (i & 15) * 4;
        float4 v = *(const float4*)(Qg + (size_t)row * HDIM + c4);
        Qs[row * LDA + c4 + 0] = f2tf32(v.x * qscale);
        Qs[row * LDA + c4 + 1] = f2tf32(v.y * qscale);
        Qs[row * LDA + c4 + 2] = f2tf32(v.z * qscale);
        Qs[row * LDA + c4 + 3] = f2tf32(v.w * qscale);
    }

    const int srow = tid >> 1, shf = tid & 1;
    float m_r = -1e30f, l_r = 0.0f;
    float acc[2][4][4];
#pragma unroll
    for (int mt = 0; mt < 2; mt++)
#pragma unroll
        for (int nt = 0; nt < 4; nt++)
#pragma unroll
            for (int e = 0; e < 4; e++) acc[mt][nt][e] = 0.0f;

    for (int kb = 0; kb < SLEN / 64; kb++) {
        __syncthreads();
        const float* Kgb = Kg + (size_t)kb * 64 * HDIM;
        const float* Vgb = Vg + (size_t)kb * 64 * HDIM;
#pragma unroll
        for (int r = 0; r < 4; r++) {
            int i = tid + r * 256;
            int row = i >> 4, c4 = (i & 15) * 4;
            float4 kv = *(const float4*)(Kgb + (size_t)row * HDIM + c4);
            float4 vv = *(const float4*)(Vgb + (size_t)row * HDIM + c4);
            Ks[row * LDA + c4 + 0] = f2tf32(kv.x);
            Ks[row * LDA + c4 + 1] = f2tf32(kv.y);
            Ks[row * LDA + c4 + 2] = f2tf32(kv.z);
            Ks[row * LDA + c4 + 3] = f2tf32(kv.w);
            Vs[row * LDA + c4 + 0] = f2tf32(vv.x);
            Vs[row * LDA + c4 + 1] = f2tf32(vv.y);
            Vs[row * LDA + c4 + 2] = f2tf32(vv.z);
            Vs[row * LDA + c4 + 3] = f2tf32(vv.w);
        }
        __syncthreads();

        float s[2][4][4];
#pragma unroll
        for (int mt = 0; mt < 2; mt++)
#pragma unroll
            for (int nt = 0; nt < 4; nt++)
#pragma unroll
                for (int e = 0; e < 4; e++) s[mt][nt][e] = 0.0f;

#pragma unroll
        for (int ks = 0; ks < 8; ks++) {
            const int kb2 = ks * 8;
            uint32_t aq[2][4];
#pragma unroll
            for (int mt = 0; mt < 2; mt++) {
                int mm = wq * 32 + mt * 16 + g;
                aq[mt][0] = Qs[mm * LDA + kb2 + t];
                aq[mt][1] = Qs[(mm + 8) * LDA + kb2 + t];
                aq[mt][2] = Qs[mm * LDA + kb2 + t + 4];
                aq[mt][3] = Qs[(mm + 8) * LDA + kb2 + t + 4];
            }
#pragma unroll
            for (int nt = 0; nt < 4; nt++) {
                int nn = wk * 32 + nt * 8 + g;
                uint32_t bk[2];
                bk[0] = Ks[nn * LDA + kb2 + t];
                bk[1] = Ks[nn * LDA + kb2 + 4 + t];
                mma_tf32(s[0][nt], aq[0], bk);
                mma_tf32(s[1][nt], aq[1], bk);
            }
        }

#pragma unroll
        for (int mt = 0; mt < 2; mt++)
#pragma unroll
            for (int nt = 0; nt < 4; nt++) {
                int r0 = wq * 32 + mt * 16 + g;
                int c0 = wk * 32 + nt * 8 + 2 * t;
                Ssf[r0 * LDA + c0]           = s[mt][nt][0];
                Ssf[r0 * LDA + c0 + 1]       = s[mt][nt][1];
                Ssf[(r0 + 8) * LDA + c0]     = s[mt][nt][2];
                Ssf[(r0 + 8) * LDA + c0 + 1] = s[mt][nt][3];
            }
        __syncthreads();

        {
            float* rowp = Ssf + srow * LDA + shf * 32;
            float4* rp4 = (float4*)rowp;
            float mx = -1e30f;
#pragma unroll
            for (int j = 0; j < 8; j++) {
                float4 v = rp4[j];
                mx = fmaxf(mx, fmaxf(fmaxf(v.x, v.y), fmaxf(v.z, v.w)));
            }
            mx = fmaxf(mx, __shfl_xor_sync(0xffffffffu, mx, 1));
            float mn = fmaxf(m_r, mx);
            float alpha = __expf(m_r - mn);
            m_r = mn;
            float sum = 0.0f;
            uint4* rpu = (uint4*)rowp;
#pragma unroll
            for (int j = 0; j < 8; j++) {
                float4 v = rp4[j];
                float e0 = __expf(v.x - mn), e1 = __expf(v.y - mn);
                float e2 = __expf(v.z - mn), e3 = __expf(v.w - mn);
                sum += (e0 + e1) + (e2 + e3);
                rpu[j] = make_uint4(f2tf32(e0), f2tf32(e1), f2tf32(e2), f2tf32(e3));
            }
            sum += __shfl_xor_sync(0xffffffffu, sum, 1);
            l_r = l_r * alpha + sum;
            if (shf == 0) alpha_sm[srow] = alpha;
        }
        __syncthreads();

#pragma unroll
        for (int mt = 0; mt < 2; mt++) {
            int r0 = wq * 32 + mt * 16 + g;
            float a0 = alpha_sm[r0], a1 = alpha_sm[r0 + 8];
#pragma unroll
            for (int nt = 0; nt < 4; nt++) {
                acc[mt][nt][0] *= a0; acc[mt][nt][1] *= a0;
                acc[mt][nt][2] *= a1; acc[mt][nt][3] *= a1;
            }
        }
#pragma unroll
        for (int ks = 0; ks < 8; ks++) {
            const int kb2 = ks * 8;
            uint32_t ap[2][4];
#pragma unroll
            for (int mt = 0; mt < 2; mt++) {
                int mm = wq * 32 + mt * 16 + g;
                ap[mt][0] = Psu[mm * LDA + kb2 + t];
                ap[mt][1] = Psu[(mm + 8) * LDA + kb2 + t];
                ap[mt][2] = Psu[mm * LDA + kb2 + t + 4];
                ap[mt][3] = Psu[(mm + 8) * LDA + kb2 + t + 4];
            }
#pragma unroll
            for (int nt = 0; nt < 4; nt++) {
                int nn = wk * 32 + nt * 8 + g;
                uint32_t bv_[2];
                bv_[0] = Vs[(kb2 + t) * LDA + nn];
                bv_[1] = Vs[(kb2 + 4 + t) * LDA + nn];
                mma_tf32(acc[0][nt], ap[0], bv_);
                mma_tf32(acc[1][nt], ap[1], bv_);
            }
        }
    }

    if (shf == 0) linv_sm[srow] = 1.0f / l_r;
    __syncthreads();

    const int b_ = bh >> 4, h = bh & 15;
#pragma unroll
    for (int mt = 0; mt < 2; mt++) {
        int r0 = wq * 32 + mt * 16 + g;
        float i0 = linv_sm[r0], i1 = linv_sm[r0 + 8];
        size_t tok0 = (size_t)b_ * SLEN + qblk * 128 + r0;
#pragma unroll
        for (int nt = 0; nt < 4; nt++) {
            int c = wk * 32 + nt * 8 + 2 * t;
            uint32_t h0, l0, h1, l1;
            split2(acc[mt][nt][0] * i0, acc[mt][nt][1] * i0, h0, l0);
            split2(acc[mt][nt][2] * i1, acc[mt][nt][3] * i1, h1, l1);
            size_t o0 = tok0 * EMBED + h * 64 + c;
            size_t o1 = (tok0 + 8) * EMBED + h * 64 + c;
            *(uint32_t*)&Oh[o0] = h0; *(uint32_t*)&Ol[o0] = l0;
            *(uint32_t*)&Oh[o1] = h1; *(uint32_t*)&Ol[o1] = l1;
        }
    }
}

// ---------------------------------------------------------------------------
extern "C" void kernel_launch(void* const* d_in, const int* in_sizes, int n_in,
                              void* d_out, int out_size)
{
    const float* x    = (const float*)d_in[0];
    const float* Wqkv = (const float*)d_in[1];
    const float* Wout = (const float*)d_in[2];
    float* out = (float*)d_out;

    float *Qp, *Kp, *Vp;
    __nv_bfloat16 *xh, *xl, *oh, *ol, *wqh, *wql, *woh, *wol;
    cudaGetSymbolAddress((void**)&Qp, g_Q);
    cudaGetSymbolAddress((void**)&Kp, g_K);
    cudaGetSymbolAddress((void**)&Vp, g_V);
    cudaGetSymbolAddress((void**)&xh, g_xh);  cudaGetSymbolAddress((void**)&xl, g_xl);
    cudaGetSymbolAddress((void**)&oh, g_oh);  cudaGetSymbolAddress((void**)&ol, g_ol);
    cudaGetSymbolAddress((void**)&wqh, g_wqh); cudaGetSymbolAddress((void**)&wql, g_wql);
    cudaGetSymbolAddress((void**)&woh, g_woh); cudaGetSymbolAddress((void**)&wol, g_wol);

    const int attn_smem = (128 * LDA + 64 * LDA + 64 * LDA + 128 * LDA + 256) * 4;
    static bool configured = false;
    if (!configured) {
        cudaFuncSetAttribute(attn_tc_kernel,
                             cudaFuncAttributeMaxDynamicSharedMemorySize, attn_smem);
        configured = true;
    }

    // 0) hi/lo splits
    int n4x = NTOK * EMBED / 4, n4q = EMBED * QKVN / 4, n4o = EMBED * EMBED / 4;
    conv_split<<<(n4x + 255) / 256, 256>>>(x, xh, xl, n4x);
    conv_split<<<(n4q + 255) / 256, 256>>>(Wqkv, wqh, wql, n4q);
    conv_split<<<(n4o + 255) / 256, 256>>>(Wout, woh, wol, n4o);

    // 1) QKV projection (bf16 3-term) + de-interleave
    dim3 g1(QKVN / 128, NTOK / 128);
    gemm_bf16_kernel<0><<<g1, 256>>>(xh, xl, wqh, wql, nullptr, Qp, Kp, Vp,
                                     NTOK, QKVN, EMBED);

    // 2) attention -> bf16 hi/lo O
    dim3 g2(SLEN / 128, BATCH * NHEAD);
    attn_tc_kernel<<<g2, 256, attn_smem>>>(Qp, Kp, Vp, oh, ol);

    // 3) output projection
    dim3 g3(EMBED / 128, NTOK / 128);
    gemm_bf16_kernel<1><<<g3, 256>>>(oh, ol, woh, wol, out, nullptr, nullptr, nullptr,
                                     NTOK, EMBED, EMBED);
}

// round 6
// speedup vs baseline: 2.0305x; 1.2068x over previous
#include <cuda_runtime.h>
#include <cuda_bf16.h>
#include <cuda_fp16.h>
#include <stdint.h>
#include <math.h>

#define BATCH 4
#define SLEN  2048
#define EMBED 1024
#define NHEAD 16
#define HDIM  64
#define NTOK  (BATCH * SLEN)     // 8192
#define QKVN  (3 * EMBED)        // 3072

__device__ float g_Q[(size_t)BATCH * NHEAD * SLEN * HDIM];
__device__ float g_K[(size_t)BATCH * NHEAD * SLEN * HDIM];
__device__ float g_V[(size_t)BATCH * NHEAD * SLEN * HDIM];
__device__ __nv_bfloat16 g_xh[(size_t)NTOK * EMBED],   g_xl[(size_t)NTOK * EMBED];
__device__ __nv_bfloat16 g_oh[(size_t)NTOK * EMBED],   g_ol[(size_t)NTOK * EMBED];
__device__ __nv_bfloat16 g_wqh[(size_t)EMBED * QKVN],  g_wql[(size_t)EMBED * QKVN];
__device__ __nv_bfloat16 g_woh[(size_t)EMBED * EMBED], g_wol[(size_t)EMBED * EMBED];

// ------------------------------ helpers ------------------------------------
__device__ __forceinline__ uint32_t s2u(const void* p) {
    uint32_t a;
    asm("{ .reg .u64 t; cvta.to.shared.u64 t, %1; cvt.u32.u64 %0, t; }" : "=r"(a) : "l"(p));
    return a;
}
__device__ __forceinline__ void mma_bf16(float* d, const uint32_t* a, const uint32_t* b) {
    asm volatile("mma.sync.aligned.m16n8k16.row.col.f32.bf16.bf16.f32 "
        "{%0,%1,%2,%3},{%4,%5,%6,%7},{%8,%9},{%0,%1,%2,%3};"
        : "+f"(d[0]), "+f"(d[1]), "+f"(d[2]), "+f"(d[3])
        : "r"(a[0]), "r"(a[1]), "r"(a[2]), "r"(a[3]), "r"(b[0]), "r"(b[1]));
}
__device__ __forceinline__ void mma_f16(float* d, const uint32_t* a, const uint32_t* b) {
    asm volatile("mma.sync.aligned.m16n8k16.row.col.f32.f16.f16.f32 "
        "{%0,%1,%2,%3},{%4,%5,%6,%7},{%8,%9},{%0,%1,%2,%3};"
        : "+f"(d[0]), "+f"(d[1]), "+f"(d[2]), "+f"(d[3])
        : "r"(a[0]), "r"(a[1]), "r"(a[2]), "r"(a[3]), "r"(b[0]), "r"(b[1]));
}
__device__ __forceinline__ void ldm_x4(uint32_t* r, uint32_t a) {
    asm volatile("ldmatrix.sync.aligned.m8n8.x4.shared.b16 {%0,%1,%2,%3},[%4];"
        : "=r"(r[0]), "=r"(r[1]), "=r"(r[2]), "=r"(r[3]) : "r"(a));
}
__device__ __forceinline__ void ldm_x2(uint32_t* r, uint32_t a) {
    asm volatile("ldmatrix.sync.aligned.m8n8.x2.shared.b16 {%0,%1},[%2];"
        : "=r"(r[0]), "=r"(r[1]) : "r"(a));
}
__device__ __forceinline__ void ldm_x2t(uint32_t* r, uint32_t a) {
    asm volatile("ldmatrix.sync.aligned.m8n8.x2.trans.shared.b16 {%0,%1},[%2];"
        : "=r"(r[0]), "=r"(r[1]) : "r"(a));
}
__device__ __forceinline__ void split2(float a, float b, uint32_t& hi, uint32_t& lo) {
    __nv_bfloat16 ha = __float2bfloat16(a), hb = __float2bfloat16(b);
    __nv_bfloat16 la = __float2bfloat16(a - __bfloat162float(ha));
    __nv_bfloat16 lb = __float2bfloat16(b - __bfloat162float(hb));
    hi = (uint32_t)__bfloat16_as_ushort(ha) | ((uint32_t)__bfloat16_as_ushort(hb) << 16);
    lo = (uint32_t)__bfloat16_as_ushort(la) | ((uint32_t)__bfloat16_as_ushort(lb) << 16);
}
#define CP16(sa, gp) \
    asm volatile("cp.async.cg.shared.global [%0], [%1], 16;" :: "r"(sa), "l"(gp) : "memory")
#define CP_COMMIT()  asm volatile("cp.async.commit_group;" ::: "memory")
#define CP_WAIT(n)   asm volatile("cp.async.wait_group %0;" :: "n"(n) : "memory")

// elementwise hi/lo split
__global__ void __launch_bounds__(256)
conv_split(const float* __restrict__ X, __nv_bfloat16* __restrict__ Xh,
           __nv_bfloat16* __restrict__ Xl, int n4)
{
    int i = blockIdx.x * blockDim.x + threadIdx.x;
    if (i >= n4) return;
    float4 v = ((const float4*)X)[i];
    uint32_t h0, l0, h1, l1;
    split2(v.x, v.y, h0, l0);
    split2(v.z, v.w, h1, l1);
    ((uint2*)Xh)[i] = make_uint2(h0, h1);
    ((uint2*)Xl)[i] = make_uint2(l0, l1);
}

// ---------------------------------------------------------------------------
// bf16 3-term GEMM with cp.async double buffering.
// C = A@B, A[M,K] hi/lo, B[K,N] hi/lo. BM=BN=128, BK=32, 256 thr, 8 warps 2x4.
// MODE 0: de-interleave scatter into Q/K/V.  MODE 1: fp32 store.
// ---------------------------------------------------------------------------
#define ALD 40
#define BLD 136
#define OFS_AL 10240
#define OFS_BH 20480
#define OFS_BL 29184
#define STG    37888
#define GEMM_SMEM (2 * STG)

template <int MODE>
__global__ void __launch_bounds__(256, 2)
gemm_bf16_kernel(const __nv_bfloat16* __restrict__ Ah, const __nv_bfloat16* __restrict__ Al,
                 const __nv_bfloat16* __restrict__ Bh, const __nv_bfloat16* __restrict__ Bl,
                 float* __restrict__ C,
                 float* __restrict__ Qo, float* __restrict__ Ko, float* __restrict__ Vo,
                 int M, int N, int K)
{
    extern __shared__ char gsm[];
    const uint32_t smb = s2u(gsm);

    const int tid = threadIdx.x, lane = tid & 31, warp = tid >> 5;
    const int wm = warp >> 2, wn = warp & 3;
    const int g = lane >> 2, t = lane & 3;
    const int m0 = blockIdx.y * 128, n0 = blockIdx.x * 128;

    const int arow = wm * 64 + (lane & 7) + ((lane >> 3) & 1) * 8;
    const int acol = (lane >> 4) * 8;
    const int krow = (lane & 7) + ((lane >> 3) & 1) * 8;

    float acc[4][4][4];
#pragma unroll
    for (int mt = 0; mt < 4; mt++)
#pragma unroll
        for (int nt = 0; nt < 4; nt++)
#pragma unroll
            for (int e = 0; e < 4; e++) acc[mt][nt][e] = 0.0f;

    const int KIT = K / 32;

    // stage loader: A 128x32, B 32x128 (hi+lo each), 8 cp.async/thread
    auto load_stage = [&](int it, uint32_t base) {
        const int k0 = it * 32;
#pragma unroll
        for (int r = 0; r < 2; r++) {
            int id = tid + r * 256;
            int row = id >> 2, ch = (id & 3) * 8;
            uint32_t da = base + (uint32_t)(row * 80 + ch * 2);
            size_t ga = (size_t)(m0 + row) * K + k0 + ch;
            CP16(da, Ah + ga);
            CP16(da + OFS_AL, Al + ga);
            int br = id >> 4, bc = (id & 15) * 8;
            uint32_t db = base + OFS_BH + (uint32_t)(br * 272 + bc * 2);
            size_t gb = (size_t)(k0 + br) * N + n0 + bc;
            CP16(db, Bh + gb);
            CP16(db + (OFS_BL - OFS_BH), Bl + gb);
        }
        CP_COMMIT();
    };

    load_stage(0, smb);

#pragma unroll 1
    for (int it = 0; it < KIT; it++) {
        const uint32_t cur = smb + (uint32_t)((it & 1) * STG);
        if (it + 1 < KIT) {
            load_stage(it + 1, smb + (uint32_t)(((it + 1) & 1) * STG));
            CP_WAIT(1);
        } else {
            CP_WAIT(0);
        }
        __syncthreads();

#pragma unroll
        for (int ks = 0; ks < 2; ks++) {
            uint32_t ah[4][4], al[4][4];
#pragma unroll
            for (int mt = 0; mt < 4; mt++) {
                uint32_t ad = cur + (uint32_t)(((arow + mt * 16) * ALD + acol + ks * 16) * 2);
                ldm_x4(ah[mt], ad);
                ldm_x4(al[mt], ad + OFS_AL);
            }
#pragma unroll
            for (int nt = 0; nt < 4; nt++) {
                int nb = wn * 32 + nt * 8;
                uint32_t bd = cur + OFS_BH + (uint32_t)(((ks * 16 + krow) * BLD + nb) * 2);
                uint32_t bh[2], bl[2];
                ldm_x2t(bh, bd);
                ldm_x2t(bl, bd + (OFS_BL - OFS_BH));
#pragma unroll
                for (int mt = 0; mt < 4; mt++) {
                    mma_bf16(acc[mt][nt], ah[mt], bh);
                    mma_bf16(acc[mt][nt], ah[mt], bl);
                    mma_bf16(acc[mt][nt], al[mt], bh);
                }
            }
        }
        __syncthreads();
    }

    if (MODE == 0) {
#pragma unroll
        for (int mt = 0; mt < 4; mt++)
#pragma unroll
            for (int nt = 0; nt < 4; nt++) {
                int r0 = m0 + wm * 64 + mt * 16 + g;
                int c0 = n0 + wn * 32 + nt * 8 + 2 * t;
#pragma unroll
                for (int e = 0; e < 4; e++) {
                    int row = r0 + (e >> 1) * 8;
                    int col = c0 + (e & 1);
                    int b_ = row >> 11, s = row & 2047;
                    int h = col / 192;
                    int rem = col - h * 192;
                    int d = rem / 3, w = rem - 3 * d;
                    float* dst = (w == 0) ? Qo : (w == 1) ? Ko : Vo;
                    dst[(((size_t)b_ * NHEAD + h) * SLEN + s) * HDIM + d] = acc[mt][nt][e];
                }
            }
    } else {
#pragma unroll
        for (int mt = 0; mt < 4; mt++)
#pragma unroll
            for (int nt = 0; nt < 4; nt++) {
                size_t r = (size_t)(m0 + wm * 64 + mt * 16 + g);
                int    c = n0 + wn * 32 + nt * 8 + 2 * t;
                *(float2*)&C[r * N + c]       = make_float2(acc[mt][nt][0], acc[mt][nt][1]);
                *(float2*)&C[(r + 8) * N + c] = make_float2(acc[mt][nt][2], acc[mt][nt][3]);
            }
    }
}

// ---------------------------------------------------------------------------
// Flash attention, fp16 m16n8k16 (same 10-bit mantissa as tf32).
// BQ=128, BKEY=64. 8 warps = 4(q) x 2(col). Epilogue -> bf16 hi/lo.
// ---------------------------------------------------------------------------
#define LDQ  72   // fp16 stride for Q/K/V/P tiles
#define LDS_S 68  // fp32 stride for score tile

__global__ void __launch_bounds__(256, 2)
attn_fp16_kernel(const float* __restrict__ Q, const float* __restrict__ K,
                 const float* __restrict__ V,
                 __nv_bfloat16* __restrict__ Oh, __nv_bfloat16* __restrict__ Ol)
{
    extern __shared__ char smc[];
    __half* Qs = (__half*)smc;                 // [128][LDQ]
    __half* Ks = Qs + 128 * LDQ;               // [64][LDQ]  (keys x d)
    __half* Vs = Ks + 64 * LDQ;                // [64][LDQ]  (keys x d)
    float*  Ssf = (float*)(Vs + 64 * LDQ);     // [128][LDS_S]
    __half* Ps = (__half*)(Ssf + 128 * LDS_S); // [128][LDQ]
    float* alpha_sm = (float*)(Ps + 128 * LDQ);
    float* linv_sm  = alpha_sm + 128;

    const int tid = threadIdx.x, lane = tid & 31, warp = tid >> 5;
    const int wq = warp >> 1, wk = warp & 1;
    const int g = lane >> 2, t = lane & 3;
    const int lr8 = (lane & 7) + ((lane >> 3) & 1) * 8;   // ldmatrix row-in-16
    const int lc8 = (lane >> 4) * 8;                      // ldmatrix col group
    const int qblk = blockIdx.x, bh = blockIdx.y;

    const float* Qg = Q + ((size_t)bh * SLEN + qblk * 128) * HDIM;
    const float* Kg = K + (size_t)bh * SLEN * HDIM;
    const float* Vg = V + (size_t)bh * SLEN * HDIM;
    const float qscale = 1.0f / 32.0f;

    // Q -> fp16 smem (scaled)
#pragma unroll
    for (int r = 0; r < 8; r++) {
        int i = tid + r * 256;
        int row = i >> 4, c4 = (i & 15) * 4;
        float4 v = *(const float4*)(Qg + (size_t)row * HDIM + c4);
        __half2 p0 = __floats2half2_rn(v.x * qscale, v.y * qscale);
        __half2 p1 = __floats2half2_rn(v.z * qscale, v.w * qscale);
        *(__half2*)(Qs + row * LDQ + c4)     = p0;
        *(__half2*)(Qs + row * LDQ + c4 + 2) = p1;
    }

    const int srow = tid >> 1, shf = tid & 1;
    float m_r = -1e30f, l_r = 0.0f;
    float acc[2][4][4];
#pragma unroll
    for (int mt = 0; mt < 2; mt++)
#pragma unroll
        for (int nt = 0; nt < 4; nt++)
#pragma unroll
            for (int e = 0; e < 4; e++) acc[mt][nt][e] = 0.0f;

    for (int kb = 0; kb < SLEN / 64; kb++) {
        __syncthreads();   // prior iteration's Ks/Vs reads complete
        const float* Kgb = Kg + (size_t)kb * 64 * HDIM;
        const float* Vgb = Vg + (size_t)kb * 64 * HDIM;
#pragma unroll
        for (int r = 0; r < 4; r++) {
            int i = tid + r * 256;
            int row = i >> 4, c4 = (i & 15) * 4;
            float4 kv = *(const float4*)(Kgb + (size_t)row * HDIM + c4);
            float4 vv = *(const float4*)(Vgb + (size_t)row * HDIM + c4);
            *(__half2*)(Ks + row * LDQ + c4)     = __floats2half2_rn(kv.x, kv.y);
            *(__half2*)(Ks + row * LDQ + c4 + 2) = __floats2half2_rn(kv.z, kv.w);
            *(__half2*)(Vs + row * LDQ + c4)     = __floats2half2_rn(vv.x, vv.y);
            *(__half2*)(Vs + row * LDQ + c4 + 2) = __floats2half2_rn(vv.z, vv.w);
        }
        __syncthreads();

        // S = Q @ K^T   (A: Qs [m][k] x4; B: Ks [n][k] x2 non-trans)
        float s[2][4][4];
#pragma unroll
        for (int mt = 0; mt < 2; mt++)
#pragma unroll
            for (int nt = 0; nt < 4; nt++)
#pragma unroll
                for (int e = 0; e < 4; e++) s[mt][nt][e] = 0.0f;

#pragma unroll
        for (int ks = 0; ks < 4; ks++) {
            uint32_t aq[2][4];
#pragma unroll
            for (int mt = 0; mt < 2; mt++)
                ldm_x4(aq[mt], s2u(Qs + (wq * 32 + mt * 16 + lr8) * LDQ + ks * 16 + lc8));
#pragma unroll
            for (int nt = 0; nt < 4; nt++) {
                uint32_t bk[2];
                ldm_x2(bk, s2u(Ks + (wk * 32 + nt * 8 + (lane & 7)) * LDQ
                                  + ks * 16 + ((lane >> 3) & 1) * 8));
                mma_f16(s[0][nt], aq[0], bk);
                mma_f16(s[1][nt], aq[1], bk);
            }
        }

        // scores -> smem fp32
#pragma unroll
        for (int mt = 0; mt < 2; mt++)
#pragma unroll
            for (int nt = 0; nt < 4; nt++) {
                int r0 = wq * 32 + mt * 16 + g;
                int c0 = wk * 32 + nt * 8 + 2 * t;
                *(float2*)&Ssf[r0 * LDS_S + c0]       = make_float2(s[mt][nt][0], s[mt][nt][1]);
                *(float2*)&Ssf[(r0 + 8) * LDS_S + c0] = make_float2(s[mt][nt][2], s[mt][nt][3]);
            }
        __syncthreads();

        // online softmax (2 threads per row), P -> fp16
        {
            float* rowp = Ssf + srow * LDS_S + shf * 32;
            float4* rp4 = (float4*)rowp;
            float mx = -1e30f;
#pragma unroll
            for (int j = 0; j < 8; j++) {
                float4 v = rp4[j];
                mx = fmaxf(mx, fmaxf(fmaxf(v.x, v.y), fmaxf(v.z, v.w)));
            }
            mx = fmaxf(mx, __shfl_xor_sync(0xffffffffu, mx, 1));
            float mn = fmaxf(m_r, mx);
            float alpha = __expf(m_r - mn);
            m_r = mn;
            float sum = 0.0f;
            __half2* pp = (__half2*)(Ps + srow * LDQ + shf * 32);
#pragma unroll
            for (int j = 0; j < 8; j++) {
                float4 v = rp4[j];
                float e0 = __expf(v.x - mn), e1 = __expf(v.y - mn);
                float e2 = __expf(v.z - mn), e3 = __expf(v.w - mn);
                sum += (e0 + e1) + (e2 + e3);
                pp[2 * j]     = __floats2half2_rn(e0, e1);
                pp[2 * j + 1] = __floats2half2_rn(e2, e3);
            }
            sum += __shfl_xor_sync(0xffffffffu, sum, 1);
            l_r = l_r * alpha + sum;
            if (shf == 0) alpha_sm[srow] = alpha;
        }
        __syncthreads();

        // rescale then O += P @ V   (A: Ps [m][k] x4; B: Vs [k][n] x2 trans)
#pragma unroll
        for (int mt = 0; mt < 2; mt++) {
            int r0 = wq * 32 + mt * 16 + g;
            float a0 = alpha_sm[r0], a1 = alpha_sm[r0 + 8];
#pragma unroll
            for (int nt = 0; nt < 4; nt++) {
                acc[mt][nt][0] *= a0; acc[mt][nt][1] *= a0;
                acc[mt][nt][2] *= a1; acc[mt][nt][3] *= a1;
            }
        }
#pragma unroll
        for (int ks = 0; ks < 4; ks++) {
            uint32_t ap[2][4];
#pragma unroll
            for (int mt = 0; mt < 2; mt++)
                ldm_x4(ap[mt], s2u(Ps + (wq * 32 + mt * 16 + lr8) * LDQ + ks * 16 + lc8));
#pragma unroll
            for (int nt = 0; nt < 4; nt++) {
                uint32_t bv[2];
                ldm_x2t(bv, s2u(Vs + (ks * 16 + lr8) * LDQ + wk * 32 + nt * 8));
                mma_f16(acc[0][nt], ap[0], bv);
                mma_f16(acc[1][nt], ap[1], bv);
            }
        }
    }

    if (shf == 0) linv_sm[srow] = 1.0f / l_r;
    __syncthreads();

    const int b_ = bh >> 4, h = bh & 15;
#pragma unroll
    for (int mt = 0; mt < 2; mt++) {
        int r0 = wq * 32 + mt * 16 + g;
        float i0 = linv_sm[r0], i1 = linv_sm[r0 + 8];
        size_t tok0 = (size_t)b_ * SLEN + qblk * 128 + r0;
#pragma unroll
        for (int nt = 0; nt < 4; nt++) {
            int c = wk * 32 + nt * 8 + 2 * t;
            uint32_t h0, l0, h1, l1;
            split2(acc[mt][nt][0] * i0, acc[mt][nt][1] * i0, h0, l0);
            split2(acc[mt][nt][2] * i1, acc[mt][nt][3] * i1, h1, l1);
            size_t o0 = tok0 * EMBED + h * 64 + c;
            size_t o1 = (tok0 + 8) * EMBED + h * 64 + c;
            *(uint32_t*)&Oh[o0] = h0; *(uint32_t*)&Ol[o0] = l0;
            *(uint32_t*)&Oh[o1] = h1; *(uint32_t*)&Ol[o1] = l1;
        }
    }
}

// ---------------------------------------------------------------------------
extern "C" void kernel_launch(void* const* d_in, const int* in_sizes, int n_in,
                              void* d_out, int out_size)
{
    const float* x    = (const float*)d_in[0];
    const float* Wqkv = (const float*)d_in[1];
    const float* Wout = (const float*)d_in[2];
    float* out = (float*)d_out;

    float *Qp, *Kp, *Vp;
    __nv_bfloat16 *xh, *xl, *oh, *ol, *wqh, *wql, *woh, *wol;
    cudaGetSymbolAddress((void**)&Qp, g_Q);
    cudaGetSymbolAddress((void**)&Kp, g_K);
    cudaGetSymbolAddress((void**)&Vp, g_V);
    cudaGetSymbolAddress((void**)&xh, g_xh);   cudaGetSymbolAddress((void**)&xl, g_xl);
    cudaGetSymbolAddress((void**)&oh, g_oh);   cudaGetSymbolAddress((void**)&ol, g_ol);
    cudaGetSymbolAddress((void**)&wqh, g_wqh); cudaGetSymbolAddress((void**)&wql, g_wql);
    cudaGetSymbolAddress((void**)&woh, g_woh); cudaGetSymbolAddress((void**)&wol, g_wol);

    const int attn_smem = 2 * (128 * LDQ) + 2 * (64 * LDQ) * 2
                        + 4 * (128 * LDS_S) + 2 * (128 * LDQ) + 4 * 256;   // 91136
    static bool configured = false;
    if (!configured) {
        cudaFuncSetAttribute(attn_fp16_kernel,
                             cudaFuncAttributeMaxDynamicSharedMemorySize, attn_smem);
        cudaFuncSetAttribute(gemm_bf16_kernel<0>,
                             cudaFuncAttributeMaxDynamicSharedMemorySize, GEMM_SMEM);
        cudaFuncSetAttribute(gemm_bf16_kernel<1>,
                             cudaFuncAttributeMaxDynamicSharedMemorySize, GEMM_SMEM);
        configured = true;
    }

    // 0) hi/lo splits
    int n4x = NTOK * EMBED / 4, n4q = EMBED * QKVN / 4, n4o = EMBED * EMBED / 4;
    conv_split<<<(n4x + 255) / 256, 256>>>(x, xh, xl, n4x);
    conv_split<<<(n4q + 255) / 256, 256>>>(Wqkv, wqh, wql, n4q);
    conv_split<<<(n4o + 255) / 256, 256>>>(Wout, woh, wol, n4o);

    // 1) QKV projection + de-interleave
    dim3 g1(QKVN / 128, NTOK / 128);
    gemm_bf16_kernel<0><<<g1, 256, GEMM_SMEM>>>(xh, xl, wqh, wql, nullptr, Qp, Kp, Vp,
                                                NTOK, QKVN, EMBED);

    // 2) fp16 flash attention -> bf16 hi/lo O
    dim3 g2(SLEN / 128, BATCH * NHEAD);
    attn_fp16_kernel<<<g2, 256, attn_smem>>>(Qp, Kp, Vp, oh, ol);

    // 3) output projection
    dim3 g3(EMBED / 128, NTOK / 128);
    gemm_bf16_kernel<1><<<g3, 256, GEMM_SMEM>>>(oh, ol, woh, wol, out, nullptr, nullptr, nullptr,
                                                NTOK, EMBED, EMBED);
}

// round 7
// speedup vs baseline: 2.9732x; 1.4643x over previous
#include <cuda_runtime.h>
#include <cuda_fp16.h>
#include <stdint.h>
#include <math.h>

#define BATCH 4
#define SLEN  2048
#define EMBED 1024
#define NHEAD 16
#define HDIM  64
#define NTOK  (BATCH * SLEN)     // 8192
#define QKVN  (3 * EMBED)        // 3072

// scratch (fp16 pipeline)
__device__ __half g_Q[(size_t)BATCH * NHEAD * SLEN * HDIM];   // pre-scaled by 1/32
__device__ __half g_K[(size_t)BATCH * NHEAD * SLEN * HDIM];
__device__ __half g_V[(size_t)BATCH * NHEAD * SLEN * HDIM];
__device__ __half g_xh[(size_t)NTOK * EMBED], g_xl[(size_t)NTOK * EMBED];
__device__ __half g_oh[(size_t)NTOK * EMBED], g_ol[(size_t)NTOK * EMBED];
__device__ __half g_w1[(size_t)EMBED * QKVN];                 // Wqkv fp16
__device__ __half g_w2[(size_t)EMBED * EMBED];                // Wout fp16

// ------------------------------ helpers ------------------------------------
__device__ __forceinline__ uint32_t s2u(const void* p) {
    uint32_t a;
    asm("{ .reg .u64 t; cvta.to.shared.u64 t, %1; cvt.u32.u64 %0, t; }" : "=r"(a) : "l"(p));
    return a;
}
__device__ __forceinline__ void mma_f16(float* d, const uint32_t* a, const uint32_t* b) {
    asm volatile("mma.sync.aligned.m16n8k16.row.col.f32.f16.f16.f32 "
        "{%0,%1,%2,%3},{%4,%5,%6,%7},{%8,%9},{%0,%1,%2,%3};"
        : "+f"(d[0]), "+f"(d[1]), "+f"(d[2]), "+f"(d[3])
        : "r"(a[0]), "r"(a[1]), "r"(a[2]), "r"(a[3]), "r"(b[0]), "r"(b[1]));
}
__device__ __forceinline__ void ldm_x4(uint32_t* r, uint32_t a) {
    asm volatile("ldmatrix.sync.aligned.m8n8.x4.shared.b16 {%0,%1,%2,%3},[%4];"
        : "=r"(r[0]), "=r"(r[1]), "=r"(r[2]), "=r"(r[3]) : "r"(a));
}
__device__ __forceinline__ void ldm_x2(uint32_t* r, uint32_t a) {
    asm volatile("ldmatrix.sync.aligned.m8n8.x2.shared.b16 {%0,%1},[%2];"
        : "=r"(r[0]), "=r"(r[1]) : "r"(a));
}
__device__ __forceinline__ void ldm_x2t(uint32_t* r, uint32_t a) {
    asm volatile("ldmatrix.sync.aligned.m8n8.x2.trans.shared.b16 {%0,%1},[%2];"
        : "=r"(r[0]), "=r"(r[1]) : "r"(a));
}
__device__ __forceinline__ uint32_t packh2(float a, float b) {
    __half2 h = __floats2half2_rn(a, b);
    return *(uint32_t*)&h;
}
__device__ __forceinline__ void split2h(float a, float b, uint32_t& hi, uint32_t& lo) {
    __half ha = __float2half_rn(a), hb = __float2half_rn(b);
    hi = (uint32_t)__half_as_ushort(ha) | ((uint32_t)__half_as_ushort(hb) << 16);
    lo = packh2(a - __half2float(ha), b - __half2float(hb));
}
#define CP16(sa, gp) \
    asm volatile("cp.async.cg.shared.global [%0], [%1], 16;" :: "r"(sa), "l"(gp) : "memory")
#define CP_COMMIT()  asm volatile("cp.async.commit_group;" ::: "memory")
#define CP_WAIT(n)   asm volatile("cp.async.wait_group %0;" :: "n"(n) : "memory")

// ------------------------- conversion kernels ------------------------------
__global__ void __launch_bounds__(256)
conv_split16(const float* __restrict__ X, __half* __restrict__ Xh,
             __half* __restrict__ Xl, int n4)
{
    int i = blockIdx.x * blockDim.x + threadIdx.x;
    if (i >= n4) return;
    float4 v = ((const float4*)X)[i];
    uint32_t h0, l0, h1, l1;
    split2h(v.x, v.y, h0, l0);
    split2h(v.z, v.w, h1, l1);
    ((uint2*)Xh)[i] = make_uint2(h0, h1);
    ((uint2*)Xl)[i] = make_uint2(l0, l1);
}
__global__ void __launch_bounds__(256)
conv_h(const float* __restrict__ X, __half* __restrict__ Y, int n4)
{
    int i = blockIdx.x * blockDim.x + threadIdx.x;
    if (i >= n4) return;
    float4 v = ((const float4*)X)[i];
    ((uint2*)Y)[i] = make_uint2(packh2(v.x, v.y), packh2(v.z, v.w));
}

// ---------------------------------------------------------------------------
// 2-term fp16 GEMM: C = (Ah+Al) @ B. BM=BN=128, BK=32, 256 thr, double buffer.
// MODE 0: de-interleave epilogue -> fp16 Q(scaled)/K/V.  MODE 1: fp32 store.
// ---------------------------------------------------------------------------
#define ALD 40
#define BLD 136
#define OFS_AL 10240
#define OFS_B  20480
#define STG    29696
#define GEMM_SMEM (2 * STG)

template <int MODE>
__global__ void __launch_bounds__(256, 2)
gemm_f16(const __half* __restrict__ Ah, const __half* __restrict__ Al,
         const __half* __restrict__ B, float* __restrict__ C,
         __half* __restrict__ Qo, __half* __restrict__ Ko, __half* __restrict__ Vo,
         int M, int N, int K)
{
    extern __shared__ char gsm[];
    const uint32_t smb = s2u(gsm);

    const int tid = threadIdx.x, lane = tid & 31, warp = tid >> 5;
    const int wm = warp >> 2, wn = warp & 3;
    const int g = lane >> 2, t = lane & 3;
    const int m0 = blockIdx.y * 128, n0 = blockIdx.x * 128;

    const int arow = wm * 64 + (lane & 7) + ((lane >> 3) & 1) * 8;
    const int acol = (lane >> 4) * 8;
    const int krow = (lane & 7) + ((lane >> 3) & 1) * 8;

    float acc[4][4][4];
#pragma unroll
    for (int mt = 0; mt < 4; mt++)
#pragma unroll
        for (int nt = 0; nt < 4; nt++)
#pragma unroll
            for (int e = 0; e < 4; e++) acc[mt][nt][e] = 0.0f;

    const int KIT = K / 32;

    auto load_stage = [&](int it, uint32_t base) {
        const int k0 = it * 32;
#pragma unroll
        for (int r = 0; r < 2; r++) {
            int id = tid + r * 256;
            int row = id >> 2, cc = id & 3;
            uint32_t da = base + (uint32_t)(row * 80 + cc * 16);
            size_t ga = (size_t)(m0 + row) * K + k0 + cc * 8;
            CP16(da, Ah + ga);
            CP16(da + OFS_AL, Al + ga);
            int br = id >> 4, bc = id & 15;
            uint32_t db = base + OFS_B + (uint32_t)(br * 272 + bc * 16);
            CP16(db, B + (size_t)(k0 + br) * N + n0 + bc * 8);
        }
        CP_COMMIT();
    };

    load_stage(0, smb);

#pragma unroll 1
    for (int it = 0; it < KIT; it++) {
        const uint32_t cur = smb + (uint32_t)((it & 1) * STG);
        if (it + 1 < KIT) {
            load_stage(it + 1, smb + (uint32_t)(((it + 1) & 1) * STG));
            CP_WAIT(1);
        } else {
            CP_WAIT(0);
        }
        __syncthreads();

#pragma unroll
        for (int ks = 0; ks < 2; ks++) {
            uint32_t ah[4][4], al[4][4];
#pragma unroll
            for (int mt = 0; mt < 4; mt++) {
                uint32_t ad = cur + (uint32_t)(((arow + mt * 16) * ALD + acol + ks * 16) * 2);
                ldm_x4(ah[mt], ad);
                ldm_x4(al[mt], ad + OFS_AL);
            }
#pragma unroll
            for (int nt = 0; nt < 4; nt++) {
                uint32_t bd = cur + OFS_B
                    + (uint32_t)(((ks * 16 + krow) * BLD + wn * 32 + nt * 8) * 2);
                uint32_t bb[2];
                ldm_x2t(bb, bd);
#pragma unroll
                for (int mt = 0; mt < 4; mt++) {
                    mma_f16(acc[mt][nt], ah[mt], bb);
                    mma_f16(acc[mt][nt], al[mt], bb);
                }
            }
        }
        __syncthreads();
    }

    if (MODE == 0) {
#pragma unroll
        for (int mt = 0; mt < 4; mt++)
#pragma unroll
            for (int nt = 0; nt < 4; nt++) {
                int r0 = m0 + wm * 64 + mt * 16 + g;
                int c0 = n0 + wn * 32 + nt * 8 + 2 * t;
#pragma unroll
                for (int e = 0; e < 4; e++) {
                    int row = r0 + (e >> 1) * 8;
                    int col = c0 + (e & 1);
                    int b_ = row >> 11, s = row & 2047;
                    int h = col / 192;
                    int rem = col - h * 192;
                    int d = rem / 3, w = rem - 3 * d;
                    __half* dst = (w == 0) ? Qo : (w == 1) ? Ko : Vo;
                    float sc = (w == 0) ? 0.03125f : 1.0f;   // fold 1/sqrt(1024) into Q
                    dst[(((size_t)b_ * NHEAD + h) * SLEN + s) * HDIM + d] =
                        __float2half_rn(acc[mt][nt][e] * sc);
                }
            }
    } else {
#pragma unroll
        for (int mt = 0; mt < 4; mt++)
#pragma unroll
            for (int nt = 0; nt < 4; nt++) {
                size_t r = (size_t)(m0 + wm * 64 + mt * 16 + g);
                int    c = n0 + wn * 32 + nt * 8 + 2 * t;
                *(float2*)&C[r * N + c]       = make_float2(acc[mt][nt][0], acc[mt][nt][1]);
                *(float2*)&C[(r + 8) * N + c] = make_float2(acc[mt][nt][2], acc[mt][nt][3]);
            }
    }
}

// ---------------------------------------------------------------------------
// Register-resident FA2. BQ=128 (8 warps x 16 rows), BKEY=64, D=64.
// S/P live in registers; K/V fp16 cp.async double-buffered.
// ---------------------------------------------------------------------------
#define LDH 72
#define ATTN_SMEM (128 * LDH * 2 + 4 * 64 * LDH * 2)   // Q + 2x(K,V) = 55296

__global__ void __launch_bounds__(256, 2)
attn_reg(const __half* __restrict__ Q, const __half* __restrict__ K,
         const __half* __restrict__ V,
         __half* __restrict__ Oh, __half* __restrict__ Ol)
{
    extern __shared__ char smc[];
    const uint32_t Qb = s2u(smc);
    const uint32_t K0 = Qb + 128 * LDH * 2;
    const uint32_t V0 = K0 + 64 * LDH * 2;
    const uint32_t K1 = V0 + 64 * LDH * 2;
    const uint32_t V1 = K1 + 64 * LDH * 2;

    const int tid = threadIdx.x, lane = tid & 31, warp = tid >> 5;
    const int g = lane >> 2, t = lane & 3;
    const int lr8 = (lane & 7) + ((lane >> 3) & 1) * 8;
    const int lc8 = (lane >> 4) * 8;
    const int qblk = blockIdx.x, bh = blockIdx.y;

    const __half* Qg = Q + ((size_t)bh * SLEN + qblk * 128) * HDIM;
    const __half* Kg = K + (size_t)bh * SLEN * HDIM;
    const __half* Vg = V + (size_t)bh * SLEN * HDIM;

    // stage Q (128x64) + K/V block 0 (64x64 each)
#pragma unroll
    for (int r = 0; r < 4; r++) {
        int id = tid + r * 256;
        int row = id >> 3, ch = id & 7;
        CP16(Qb + row * 144 + ch * 16, Qg + row * 64 + ch * 8);
    }
#pragma unroll
    for (int r = 0; r < 2; r++) {
        int id = tid + r * 256;
        int row = id >> 3, ch = id & 7;
        CP16(K0 + row * 144 + ch * 16, Kg + row * 64 + ch * 8);
        CP16(V0 + row * 144 + ch * 16, Vg + row * 64 + ch * 8);
    }
    CP_COMMIT();
    CP_WAIT(0);
    __syncthreads();

    uint32_t qf[4][4];
#pragma unroll
    for (int kt = 0; kt < 4; kt++)
        ldm_x4(qf[kt], Qb + (uint32_t)(((warp * 16 + lr8) * LDH + kt * 16 + lc8) * 2));

    float m0 = -1e30f, m1 = -1e30f, l0 = 0.0f, l1 = 0.0f;
    float o[8][4];
#pragma unroll
    for (int nt = 0; nt < 8; nt++)
#pragma unroll
        for (int e = 0; e < 4; e++) o[nt][e] = 0.0f;

#pragma unroll 1
    for (int kb = 0; kb < SLEN / 64; kb++) {
        const uint32_t Kc = (kb & 1) ? K1 : K0;
        const uint32_t Vc = (kb & 1) ? V1 : V0;
        if (kb + 1 < SLEN / 64) {
            const uint32_t Kn = (kb & 1) ? K0 : K1;
            const uint32_t Vn = (kb & 1) ? V0 : V1;
            const __half* Kgn = Kg + (size_t)(kb + 1) * 64 * HDIM;
            const __half* Vgn = Vg + (size_t)(kb + 1) * 64 * HDIM;
#pragma unroll
            for (int r = 0; r < 2; r++) {
                int id = tid + r * 256;
                int row = id >> 3, ch = id & 7;
                CP16(Kn + row * 144 + ch * 16, Kgn + row * 64 + ch * 8);
                CP16(Vn + row * 144 + ch * 16, Vgn + row * 64 + ch * 8);
            }
            CP_COMMIT();
            CP_WAIT(1);
        } else {
            CP_WAIT(0);
        }
        __syncthreads();

        // S = Q @ K^T  (16 x 64 per warp, registers)
        float s[8][4];
#pragma unroll
        for (int nt = 0; nt < 8; nt++)
#pragma unroll
            for (int e = 0; e < 4; e++) s[nt][e] = 0.0f;
#pragma unroll
        for (int kt = 0; kt < 4; kt++)
#pragma unroll
            for (int nt = 0; nt < 8; nt++) {
                uint32_t bk[2];
                ldm_x2(bk, Kc + (uint32_t)(((nt * 8 + (lane & 7)) * LDH
                                            + kt * 16 + ((lane >> 3) & 1) * 8) * 2));
                mma_f16(s[nt], qf[kt], bk);
            }

        // online softmax in registers (rows g, g+8 of this warp's 16)
        float mx0 = -1e30f, mx1 = -1e30f;
#pragma unroll
        for (int nt = 0; nt < 8; nt++) {
            mx0 = fmaxf(mx0, fmaxf(s[nt][0], s[nt][1]));
            mx1 = fmaxf(mx1, fmaxf(s[nt][2], s[nt][3]));
        }
        mx0 = fmaxf(mx0, __shfl_xor_sync(0xffffffffu, mx0, 1));
        mx0 = fmaxf(mx0, __shfl_xor_sync(0xffffffffu, mx0, 2));
        mx1 = fmaxf(mx1, __shfl_xor_sync(0xffffffffu, mx1, 1));
        mx1 = fmaxf(mx1, __shfl_xor_sync(0xffffffffu, mx1, 2));
        float mn0 = fmaxf(m0, mx0), mn1 = fmaxf(m1, mx1);
        float a0 = __expf(m0 - mn0), a1 = __expf(m1 - mn1);
        m0 = mn0; m1 = mn1;

        float sum0 = 0.0f, sum1 = 0.0f;
        uint32_t pf[4][4];
#pragma unroll
        for (int nt = 0; nt < 8; nt++) {
            float e0 = __expf(s[nt][0] - mn0), e1 = __expf(s[nt][1] - mn0);
            float e2 = __expf(s[nt][2] - mn1), e3 = __expf(s[nt][3] - mn1);
            sum0 += e0 + e1; sum1 += e2 + e3;
            uint32_t p01 = packh2(e0, e1), p23 = packh2(e2, e3);
            int kt = nt >> 1;
            if (nt & 1) { pf[kt][2] = p01; pf[kt][3] = p23; }
            else        { pf[kt][0] = p01; pf[kt][1] = p23; }
        }
        sum0 += __shfl_xor_sync(0xffffffffu, sum0, 1);
        sum0 += __shfl_xor_sync(0xffffffffu, sum0, 2);
        sum1 += __shfl_xor_sync(0xffffffffu, sum1, 1);
        sum1 += __shfl_xor_sync(0xffffffffu, sum1, 2);
        l0 = l0 * a0 + sum0;
        l1 = l1 * a1 + sum1;

#pragma unroll
        for (int nt = 0; nt < 8; nt++) {
            o[nt][0] *= a0; o[nt][1] *= a0;
            o[nt][2] *= a1; o[nt][3] *= a1;
        }
        // O += P @ V
#pragma unroll
        for (int kt = 0; kt < 4; kt++)
#pragma unroll
            for (int nt = 0; nt < 8; nt++) {
                uint32_t bv[2];
                ldm_x2t(bv, Vc + (uint32_t)(((kt * 16 + lr8) * LDH + nt * 8) * 2));
                mma_f16(o[nt], pf[kt], bv);
            }
        __syncthreads();
    }

    const float i0 = 1.0f / l0, i1 = 1.0f / l1;
    const int b_ = bh >> 4, h = bh & 15;
    const int r0 = qblk * 128 + warp * 16 + g;
    const size_t tok0 = (size_t)b_ * SLEN + r0;
#pragma unroll
    for (int nt = 0; nt < 8; nt++) {
        int c = nt * 8 + 2 * t;
        uint32_t h0, lo0, h1, lo1;
        split2h(o[nt][0] * i0, o[nt][1] * i0, h0, lo0);
        split2h(o[nt][2] * i1, o[nt][3] * i1, h1, lo1);
        size_t a0i = tok0 * EMBED + h * 64 + c;
        size_t a1i = (tok0 + 8) * EMBED + h * 64 + c;
        *(uint32_t*)&Oh[a0i] = h0;  *(uint32_t*)&Ol[a0i] = lo0;
        *(uint32_t*)&Oh[a1i] = h1;  *(uint32_t*)&Ol[a1i] = lo1;
    }
}

// ---------------------------------------------------------------------------
extern "C" void kernel_launch(void* const* d_in, const int* in_sizes, int n_in,
                              void* d_out, int out_size)
{
    const float* x    = (const float*)d_in[0];
    const float* Wqkv = (const float*)d_in[1];
    const float* Wout = (const float*)d_in[2];
    float* out = (float*)d_out;

    __half *Qp, *Kp, *Vp, *xh, *xl, *oh, *ol, *w1, *w2;
    cudaGetSymbolAddress((void**)&Qp, g_Q);
    cudaGetSymbolAddress((void**)&Kp, g_K);
    cudaGetSymbolAddress((void**)&Vp, g_V);
    cudaGetSymbolAddress((void**)&xh, g_xh);  cudaGetSymbolAddress((void**)&xl, g_xl);
    cudaGetSymbolAddress((void**)&oh, g_oh);  cudaGetSymbolAddress((void**)&ol, g_ol);
    cudaGetSymbolAddress((void**)&w1, g_w1);  cudaGetSymbolAddress((void**)&w2, g_w2);

    static bool configured = false;
    if (!configured) {
        cudaFuncSetAttribute(attn_reg,
                             cudaFuncAttributeMaxDynamicSharedMemorySize, ATTN_SMEM);
        cudaFuncSetAttribute(gemm_f16<0>,
                             cudaFuncAttributeMaxDynamicSharedMemorySize, GEMM_SMEM);
        cudaFuncSetAttribute(gemm_f16<1>,
                             cudaFuncAttributeMaxDynamicSharedMemorySize, GEMM_SMEM);
        configured = true;
    }

    // 0) conversions
    int n4x = NTOK * EMBED / 4, n4q = EMBED * QKVN / 4, n4o = EMBED * EMBED / 4;
    conv_split16<<<(n4x + 255) / 256, 256>>>(x, xh, xl, n4x);
    conv_h<<<(n4q + 255) / 256, 256>>>(Wqkv, w1, n4q);
    conv_h<<<(n4o + 255) / 256, 256>>>(Wout, w2, n4o);

    // 1) QKV projection -> fp16 Q(scaled)/K/V
    dim3 g1(QKVN / 128, NTOK / 128);
    gemm_f16<0><<<g1, 256, GEMM_SMEM>>>(xh, xl, w1, nullptr, Qp, Kp, Vp,
                                        NTOK, QKVN, EMBED);

    // 2) register FA2 -> fp16 hi/lo O
    dim3 g2(SLEN / 128, BATCH * NHEAD);
    attn_reg<<<g2, 256, ATTN_SMEM>>>(Qp, Kp, Vp, oh, ol);

    // 3) output projection
    dim3 g3(EMBED / 128, NTOK / 128);
    gemm_f16<1><<<g3, 256, GEMM_SMEM>>>(oh, ol, w2, out, nullptr, nullptr, nullptr,
                                        NTOK, EMBED, EMBED);
}

// round 8
// speedup vs baseline: 3.2598x; 1.0964x over previous
#include <cuda_runtime.h>
#include <cuda_fp16.h>
#include <stdint.h>
#include <math.h>

#define BATCH 4
#define SLEN  2048
#define EMBED 1024
#define NHEAD 16
#define HDIM  64
#define NTOK  (BATCH * SLEN)     // 8192
#define QKVN  (3 * EMBED)        // 3072

__device__ __half g_Q[(size_t)BATCH * NHEAD * SLEN * HDIM];   // pre-scaled by 1/32
__device__ __half g_K[(size_t)BATCH * NHEAD * SLEN * HDIM];
__device__ __half g_V[(size_t)BATCH * NHEAD * SLEN * HDIM];
__device__ __half g_xh[(size_t)NTOK * EMBED], g_xl[(size_t)NTOK * EMBED];
__device__ __half g_o[(size_t)NTOK * EMBED];
__device__ __half g_w1[(size_t)EMBED * QKVN];
__device__ __half g_w2[(size_t)EMBED * EMBED];

// ------------------------------ helpers ------------------------------------
__device__ __forceinline__ uint32_t s2u(const void* p) {
    uint32_t a;
    asm("{ .reg .u64 t; cvta.to.shared.u64 t, %1; cvt.u32.u64 %0, t; }" : "=r"(a) : "l"(p));
    return a;
}
__device__ __forceinline__ void mma_f16(float* d, const uint32_t* a, const uint32_t* b) {
    asm volatile("mma.sync.aligned.m16n8k16.row.col.f32.f16.f16.f32 "
        "{%0,%1,%2,%3},{%4,%5,%6,%7},{%8,%9},{%0,%1,%2,%3};"
        : "+f"(d[0]), "+f"(d[1]), "+f"(d[2]), "+f"(d[3])
        : "r"(a[0]), "r"(a[1]), "r"(a[2]), "r"(a[3]), "r"(b[0]), "r"(b[1]));
}
__device__ __forceinline__ void ldm_x4(uint32_t* r, uint32_t a) {
    asm volatile("ldmatrix.sync.aligned.m8n8.x4.shared.b16 {%0,%1,%2,%3},[%4];"
        : "=r"(r[0]), "=r"(r[1]), "=r"(r[2]), "=r"(r[3]) : "r"(a));
}
__device__ __forceinline__ void ldm_x4t(uint32_t* r, uint32_t a) {
    asm volatile("ldmatrix.sync.aligned.m8n8.x4.trans.shared.b16 {%0,%1,%2,%3},[%4];"
        : "=r"(r[0]), "=r"(r[1]), "=r"(r[2]), "=r"(r[3]) : "r"(a));
}
__device__ __forceinline__ uint32_t packh2(float a, float b) {
    __half2 h = __floats2half2_rn(a, b);
    return *(uint32_t*)&h;
}
__device__ __forceinline__ void split2h(float a, float b, uint32_t& hi, uint32_t& lo) {
    __half ha = __float2half_rn(a), hb = __float2half_rn(b);
    hi = (uint32_t)__half_as_ushort(ha) | ((uint32_t)__half_as_ushort(hb) << 16);
    lo = packh2(a - __half2float(ha), b - __half2float(hb));
}
#define CP16(sa, gp) \
    asm volatile("cp.async.cg.shared.global [%0], [%1], 16;" :: "r"(sa), "l"(gp) : "memory")
#define CP_COMMIT()  asm volatile("cp.async.commit_group;" ::: "memory")
#define CP_WAIT(n)   asm volatile("cp.async.wait_group %0;" :: "n"(n) : "memory")

// ------------------------- conversion kernels ------------------------------
__global__ void __launch_bounds__(256)
conv_split16(const float* __restrict__ X, __half* __restrict__ Xh,
             __half* __restrict__ Xl, int n4)
{
    int i = blockIdx.x * blockDim.x + threadIdx.x;
    if (i >= n4) return;
    float4 v = ((const float4*)X)[i];
    uint32_t h0, l0, h1, l1;
    split2h(v.x, v.y, h0, l0);
    split2h(v.z, v.w, h1, l1);
    ((uint2*)Xh)[i] = make_uint2(h0, h1);
    ((uint2*)Xl)[i] = make_uint2(l0, l1);
}
__global__ void __launch_bounds__(256)
conv_h(const float* __restrict__ X, __half* __restrict__ Y, int n4)
{
    int i = blockIdx.x * blockDim.x + threadIdx.x;
    if (i >= n4) return;
    float4 v = ((const float4*)X)[i];
    ((uint2*)Y)[i] = make_uint2(packh2(v.x, v.y), packh2(v.z, v.w));
}

// ---------------------------------------------------------------------------
// fp16 GEMM, TERMS-term A (hi[+lo]), 3-stage cp.async pipeline.
// BM=BN=128, BK=32, 256 thr, 8 warps 2x4 (warp 64x32).
// MODE 0: de-interleave epilogue -> fp16 Q(scaled)/K/V.  MODE 1: fp32 store.
// ---------------------------------------------------------------------------
#define OFS_AL 10240

template <int MODE, int TERMS>
__global__ void __launch_bounds__(256, 2)
gemm_f16(const __half* __restrict__ Ah, const __half* __restrict__ Al,
         const __half* __restrict__ B, float* __restrict__ C,
         __half* __restrict__ Qo, __half* __restrict__ Ko, __half* __restrict__ Vo,
         int M, int N, int K)
{
    constexpr uint32_t OFSB = (TERMS == 2) ? 20480u : 10240u;
    constexpr uint32_t STGB = (TERMS == 2) ? 29696u : 19456u;

    extern __shared__ char gsm[];
    const uint32_t smb = s2u(gsm);

    const int tid = threadIdx.x, lane = tid & 31, warp = tid >> 5;
    const int wm = warp >> 2, wn = warp & 3;
    const int g = lane >> 2, t = lane & 3;
    const int m0 = blockIdx.y * 128, n0 = blockIdx.x * 128;

    const int arow = wm * 64 + (lane & 7) + ((lane >> 3) & 1) * 8;
    const int acol = (lane >> 4) * 8;
    // B x4-trans lane addressing (two n8 fragments per call)
    const int brow = (lane & 7) + ((lane >> 3) & 1) * 8;
    const int bcol = (lane >> 4) * 8;

    float acc[4][4][4];
#pragma unroll
    for (int mt = 0; mt < 4; mt++)
#pragma unroll
        for (int nt = 0; nt < 4; nt++)
#pragma unroll
            for (int e = 0; e < 4; e++) acc[mt][nt][e] = 0.0f;

    const int KIT = K / 32;

    auto load_stage = [&](int it) {
        const uint32_t base = smb + (uint32_t)(it % 3) * STGB;
        const int k0 = it * 32;
#pragma unroll
        for (int r = 0; r < 2; r++) {
            int id = tid + r * 256;
            int row = id >> 2, cc = id & 3;
            uint32_t da = base + (uint32_t)(row * 80 + cc * 16);
            size_t ga = (size_t)(m0 + row) * K + k0 + cc * 8;
            CP16(da, Ah + ga);
            if (TERMS == 2) CP16(da + OFS_AL, Al + ga);
            int br = id >> 4, bc = id & 15;
            CP16(base + OFSB + (uint32_t)(br * 272 + bc * 16),
                 B + (size_t)(k0 + br) * N + n0 + bc * 8);
        }
        CP_COMMIT();
    };

    load_stage(0);
    load_stage(1);

#pragma unroll 1
    for (int it = 0; it < KIT; it++) {
        const uint32_t cur = smb + (uint32_t)(it % 3) * STGB;
        if (it + 2 < KIT) { load_stage(it + 2); CP_WAIT(2); }
        else if (it + 1 < KIT) { CP_WAIT(1); }
        else { CP_WAIT(0); }
        __syncthreads();

#pragma unroll
        for (int ks = 0; ks < 2; ks++) {
            uint32_t ah[4][4], al[4][4];
#pragma unroll
            for (int mt = 0; mt < 4; mt++) {
                uint32_t ad = cur + (uint32_t)(((arow + mt * 16) * 40 + acol + ks * 16) * 2);
                ldm_x4(ah[mt], ad);
                if (TERMS == 2) ldm_x4(al[mt], ad + OFS_AL);
            }
            uint32_t bb[2][4];
#pragma unroll
            for (int p = 0; p < 2; p++)
                ldm_x4t(bb[p], cur + OFSB
                        + (uint32_t)((ks * 16 + brow) * 272
                                     + (wn * 32 + p * 16 + bcol) * 2));
#pragma unroll
            for (int p = 0; p < 2; p++)
#pragma unroll
                for (int sub = 0; sub < 2; sub++) {
                    const int nt = 2 * p + sub;
#pragma unroll
                    for (int mt = 0; mt < 4; mt++) {
                        mma_f16(acc[mt][nt], ah[mt], &bb[p][sub * 2]);
                        if (TERMS == 2) mma_f16(acc[mt][nt], al[mt], &bb[p][sub * 2]);
                    }
                }
        }
        __syncthreads();
    }

    if (MODE == 0) {
#pragma unroll
        for (int mt = 0; mt < 4; mt++)
#pragma unroll
            for (int nt = 0; nt < 4; nt++) {
                int r0 = m0 + wm * 64 + mt * 16 + g;
                int c0 = n0 + wn * 32 + nt * 8 + 2 * t;
#pragma unroll
                for (int e = 0; e < 4; e++) {
                    int row = r0 + (e >> 1) * 8;
                    int col = c0 + (e & 1);
                    int b_ = row >> 11, s = row & 2047;
                    int h = col / 192;
                    int rem = col - h * 192;
                    int d = rem / 3, w = rem - 3 * d;
                    __half* dst = (w == 0) ? Qo : (w == 1) ? Ko : Vo;
                    float sc = (w == 0) ? 0.03125f : 1.0f;
                    dst[(((size_t)b_ * NHEAD + h) * SLEN + s) * HDIM + d] =
                        __float2half_rn(acc[mt][nt][e] * sc);
                }
            }
    } else {
#pragma unroll
        for (int mt = 0; mt < 4; mt++)
#pragma unroll
            for (int nt = 0; nt < 4; nt++) {
                size_t r = (size_t)(m0 + wm * 64 + mt * 16 + g);
                int    c = n0 + wn * 32 + nt * 8 + 2 * t;
                *(float2*)&C[r * N + c]       = make_float2(acc[mt][nt][0], acc[mt][nt][1]);
                *(float2*)&C[(r + 8) * N + c] = make_float2(acc[mt][nt][2], acc[mt][nt][3]);
            }
    }
}

// ---------------------------------------------------------------------------
// Register FA2: BQ=128 (8 warps x 16 rows), BKEY=64, D=64.
// K/V 3-stage cp.async pipeline; S/P register-resident; x4 operand fetches.
// ---------------------------------------------------------------------------
#define LDHB 144                                  // bytes per row (72 halfs)
#define KVST (2 * 64 * LDHB)                      // K+V per stage = 18432
#define ATTN_SMEM (128 * LDHB + 3 * KVST)         // Q + 3 stages = 73728

__global__ void __launch_bounds__(256, 2)
attn_reg(const __half* __restrict__ Q, const __half* __restrict__ K,
         const __half* __restrict__ V, __half* __restrict__ O)
{
    extern __shared__ char smc[];
    const uint32_t Qb = s2u(smc);
    const uint32_t KV0 = Qb + 128 * LDHB;

    const int tid = threadIdx.x, lane = tid & 31, warp = tid >> 5;
    const int g = lane >> 2, t = lane & 3;
    const int lr8 = (lane & 7) + ((lane >> 3) & 1) * 8;
    const int lc8 = (lane >> 4) * 8;
    const int qblk = blockIdx.x, bh = blockIdx.y;

    const __half* Qg = Q + ((size_t)bh * SLEN + qblk * 128) * HDIM;
    const __half* Kg = K + (size_t)bh * SLEN * HDIM;
    const __half* Vg = V + (size_t)bh * SLEN * HDIM;

    auto load_kv = [&](int kb) {
        const uint32_t base = KV0 + (uint32_t)(kb % 3) * KVST;
        const __half* Kgb = Kg + (size_t)kb * 64 * HDIM;
        const __half* Vgb = Vg + (size_t)kb * 64 * HDIM;
#pragma unroll
        for (int r = 0; r < 2; r++) {
            int id = tid + r * 256;
            int row = id >> 3, ch = id & 7;
            CP16(base + row * LDHB + ch * 16, Kgb + row * 64 + ch * 8);
            CP16(base + 64 * LDHB + row * LDHB + ch * 16, Vgb + row * 64 + ch * 8);
        }
        CP_COMMIT();
    };

    // Q + stages 0,1
#pragma unroll
    for (int r = 0; r < 4; r++) {
        int id = tid + r * 256;
        int row = id >> 3, ch = id & 7;
        CP16(Qb + row * LDHB + ch * 16, Qg + row * 64 + ch * 8);
    }
    CP_COMMIT();
    load_kv(0);
    load_kv(1);
    CP_WAIT(2);             // Q resident
    __syncthreads();

    uint32_t qf[4][4];
#pragma unroll
    for (int kt = 0; kt < 4; kt++)
        ldm_x4(qf[kt], Qb + (uint32_t)((warp * 16 + lr8) * LDHB + (kt * 16 + lc8) * 2));

    float m0 = -1e30f, m1 = -1e30f, l0 = 0.0f, l1 = 0.0f;
    float o[8][4];
#pragma unroll
    for (int nt = 0; nt < 8; nt++)
#pragma unroll
        for (int e = 0; e < 4; e++) o[nt][e] = 0.0f;

    const int NKB = SLEN / 64;
#pragma unroll 1
    for (int kb = 0; kb < NKB; kb++) {
        const uint32_t Kc = KV0 + (uint32_t)(kb % 3) * KVST;
        const uint32_t Vc = Kc + 64 * LDHB;
        if (kb + 2 < NKB) { load_kv(kb + 2); CP_WAIT(2); }
        else if (kb + 1 < NKB) { CP_WAIT(1); }
        else { CP_WAIT(0); }
        __syncthreads();

        // S = Q @ K^T
        float s[8][4];
#pragma unroll
        for (int nt = 0; nt < 8; nt++)
#pragma unroll
            for (int e = 0; e < 4; e++) s[nt][e] = 0.0f;
#pragma unroll
        for (int kt = 0; kt < 4; kt++)
#pragma unroll
            for (int p = 0; p < 4; p++) {
                uint32_t bk[4];
                ldm_x4(bk, Kc + (uint32_t)((p * 16 + lc8 + (lane & 7)) * LDHB
                                           + (kt * 16 + ((lane >> 3) & 1) * 8) * 2));
                mma_f16(s[2 * p],     qf[kt], &bk[0]);
                mma_f16(s[2 * p + 1], qf[kt], &bk[2]);
            }

        // online softmax (register rows g, g+8)
        float mx0 = -1e30f, mx1 = -1e30f;
#pragma unroll
        for (int nt = 0; nt < 8; nt++) {
            mx0 = fmaxf(mx0, fmaxf(s[nt][0], s[nt][1]));
            mx1 = fmaxf(mx1, fmaxf(s[nt][2], s[nt][3]));
        }
        mx0 = fmaxf(mx0, __shfl_xor_sync(0xffffffffu, mx0, 1));
        mx0 = fmaxf(mx0, __shfl_xor_sync(0xffffffffu, mx0, 2));
        mx1 = fmaxf(mx1, __shfl_xor_sync(0xffffffffu, mx1, 1));
        mx1 = fmaxf(mx1, __shfl_xor_sync(0xffffffffu, mx1, 2));
        float mn0 = fmaxf(m0, mx0), mn1 = fmaxf(m1, mx1);
        float a0 = __expf(m0 - mn0), a1 = __expf(m1 - mn1);
        m0 = mn0; m1 = mn1;

        float sum0 = 0.0f, sum1 = 0.0f;
        uint32_t pf[4][4];
#pragma unroll
        for (int nt = 0; nt < 8; nt++) {
            float e0 = __expf(s[nt][0] - mn0), e1 = __expf(s[nt][1] - mn0);
            float e2 = __expf(s[nt][2] - mn1), e3 = __expf(s[nt][3] - mn1);
            sum0 += e0 + e1; sum1 += e2 + e3;
            uint32_t p01 = packh2(e0, e1), p23 = packh2(e2, e3);
            int kt = nt >> 1;
            if (nt & 1) { pf[kt][2] = p01; pf[kt][3] = p23; }
            else        { pf[kt][0] = p01; pf[kt][1] = p23; }
        }
        sum0 += __shfl_xor_sync(0xffffffffu, sum0, 1);
        sum0 += __shfl_xor_sync(0xffffffffu, sum0, 2);
        sum1 += __shfl_xor_sync(0xffffffffu, sum1, 1);
        sum1 += __shfl_xor_sync(0xffffffffu, sum1, 2);
        l0 = l0 * a0 + sum0;
        l1 = l1 * a1 + sum1;

#pragma unroll
        for (int nt = 0; nt < 8; nt++) {
            o[nt][0] *= a0; o[nt][1] *= a0;
            o[nt][2] *= a1; o[nt][3] *= a1;
        }
        // O += P @ V
#pragma unroll
        for (int kt = 0; kt < 4; kt++)
#pragma unroll
            for (int p = 0; p < 4; p++) {
                uint32_t bv[4];
                ldm_x4t(bv, Vc + (uint32_t)((kt * 16 + lr8) * LDHB
                                            + (p * 16 + lc8) * 2));
                mma_f16(o[2 * p],     pf[kt], &bv[0]);
                mma_f16(o[2 * p + 1], pf[kt], &bv[2]);
            }
        __syncthreads();
    }

    const float i0 = 1.0f / l0, i1 = 1.0f / l1;
    const int b_ = bh >> 4, h = bh & 15;
    const int r0 = qblk * 128 + warp * 16 + g;
    const size_t tok0 = (size_t)b_ * SLEN + r0;
#pragma unroll
    for (int nt = 0; nt < 8; nt++) {
        int c = nt * 8 + 2 * t;
        *(uint32_t*)&O[tok0 * EMBED + h * 64 + c] =
            packh2(o[nt][0] * i0, o[nt][1] * i0);
        *(uint32_t*)&O[(tok0 + 8) * EMBED + h * 64 + c] =
            packh2(o[nt][2] * i1, o[nt][3] * i1);
    }
}

// ---------------------------------------------------------------------------
extern "C" void kernel_launch(void* const* d_in, const int* in_sizes, int n_in,
                              void* d_out, int out_size)
{
    const float* x    = (const float*)d_in[0];
    const float* Wqkv = (const float*)d_in[1];
    const float* Wout = (const float*)d_in[2];
    float* out = (float*)d_out;

    __half *Qp, *Kp, *Vp, *xh, *xl, *op, *w1, *w2;
    cudaGetSymbolAddress((void**)&Qp, g_Q);
    cudaGetSymbolAddress((void**)&Kp, g_K);
    cudaGetSymbolAddress((void**)&Vp, g_V);
    cudaGetSymbolAddress((void**)&xh, g_xh);  cudaGetSymbolAddress((void**)&xl, g_xl);
    cudaGetSymbolAddress((void**)&op, g_o);
    cudaGetSymbolAddress((void**)&w1, g_w1);  cudaGetSymbolAddress((void**)&w2, g_w2);

    const int smem2 = 3 * 29696;   // TERMS=2 pipeline
    const int smem1 = 3 * 19456;   // TERMS=1 pipeline
    static bool configured = false;
    if (!configured) {
        cudaFuncSetAttribute(attn_reg,
                             cudaFuncAttributeMaxDynamicSharedMemorySize, ATTN_SMEM);
        cudaFuncSetAttribute(gemm_f16<0, 2>,
                             cudaFuncAttributeMaxDynamicSharedMemorySize, smem2);
        cudaFuncSetAttribute(gemm_f16<1, 1>,
                             cudaFuncAttributeMaxDynamicSharedMemorySize, smem1);
        configured = true;
    }

    // 0) conversions
    int n4x = NTOK * EMBED / 4, n4q = EMBED * QKVN / 4, n4o = EMBED * EMBED / 4;
    conv_split16<<<(n4x + 255) / 256, 256>>>(x, xh, xl, n4x);
    conv_h<<<(n4q + 255) / 256, 256>>>(Wqkv, w1, n4q);
    conv_h<<<(n4o + 255) / 256, 256>>>(Wout, w2, n4o);

    // 1) QKV projection (2-term) -> fp16 Q(scaled)/K/V
    dim3 g1(QKVN / 128, NTOK / 128);
    gemm_f16<0, 2><<<g1, 256, smem2>>>(xh, xl, w1, nullptr, Qp, Kp, Vp,
                                       NTOK, QKVN, EMBED);

    // 2) register FA2 -> fp16 O
    dim3 g2(SLEN / 128, BATCH * NHEAD);
    attn_reg<<<g2, 256, ATTN_SMEM>>>(Qp, Kp, Vp, op);

    // 3) output projection (1-term)
    dim3 g3(EMBED / 128, NTOK / 128);
    gemm_f16<1, 1><<<g3, 256, smem1>>>(op, nullptr, w2, out, nullptr, nullptr, nullptr,
                                       NTOK, EMBED, EMBED);
}